// round 14
// baseline (speedup 1.0000x reference)
#include <cuda_runtime.h>
#include <cuda_bf16.h>
#include <math.h>

#define NN 50000
#define EE 800000
#define DD 96
#define HIDN 128
#define OUTN 8
#define NBS 196    // scan blocks = ceil(NN/256)
#define WSTR 104   // bf16 smem stride (elements) for W^T  — conflict-free (edge)
#define ESTRB 104  // bf16 smem stride (elements) for E tile (edge)
#define XSTR 108   // f32/tf32 smem stride for X tile (mat kernels)
#define WS2 200    // f32/tf32 smem stride for 2-matrix concat W (mat kernels)
#define EMB_BLKS 18750  // (NN*DD+255)/256
#define ETILE 256

typedef unsigned long long ull;

// ------------------------- device scratch (no allocs allowed) ----------------
__device__ float g_h[(size_t)NN * DD];
__device__ float g_hnew[(size_t)NN * DD];
__device__ float g_A[(size_t)NN * DD];             // f32 (residual-critical)
__device__ __nv_bfloat16 g_B[(size_t)NN * DD];     // gathered tables in bf16
__device__ __nv_bfloat16 g_D[(size_t)NN * DD];
__device__ __nv_bfloat16 g_E[(size_t)NN * DD];
__device__ __nv_bfloat16 g_e[(size_t)EE * DD];     // permuted (CSR dst order)
__device__ __nv_bfloat16 g_enew[(size_t)EE * DD];  // permuted
__device__ __nv_bfloat16 g_WtC[4 * DD * DD];       // pre-transposed bf16 WC per layer
__device__ float g_WDE[4 * DD * 192];              // tf32-prerounded [WD|WE] per layer
__device__ float g_WAB[4 * DD * 192];              // tf32-prerounded [WA|WB] per layer
__device__ int   g_cnt[NN];
__device__ int   g_ptr[NN + 1];
__device__ int   g_woff[NN];
__device__ int   g_eid[EE];
__device__ int   g_srcp[EE];
__device__ int   g_dstp[EE];
__device__ int   g_bsum[256];
__device__ int   g_boff[256];
// layer-indexed stats (no reset races)
__device__ double g_esum[4 * DD], g_esq[4 * DD], g_hsum[4 * DD], g_hsq[4 * DD];

// ------------------------- helpers -------------------------------------------
__device__ __forceinline__ ull pk2(float lo, float hi) {
    ull r; asm("mov.b64 %0,{%1,%2};" : "=l"(r) : "f"(lo), "f"(hi)); return r;
}
__device__ __forceinline__ ull fma2(ull a, ull b, ull c) {
    ull d; asm("fma.rn.f32x2 %0,%1,%2,%3;" : "=l"(d) : "l"(a), "l"(b), "l"(c)); return d;
}
__device__ __forceinline__ float2 upk(ull v) {
    float2 f; asm("mov.b64 {%0,%1},%2;" : "=f"(f.x), "=f"(f.y) : "l"(v)); return f;
}
__device__ __forceinline__ float tf32r(float x) {
    unsigned u; asm("cvt.rna.tf32.f32 %0,%1;" : "=r"(u) : "f"(x));
    return __uint_as_float(u);
}
#define MMA_TF32(d, a, b0_, b1_) \
    asm volatile("mma.sync.aligned.m16n8k8.row.col.f32.tf32.tf32.f32 " \
        "{%0,%1,%2,%3},{%4,%5,%6,%7},{%8,%9},{%0,%1,%2,%3};" \
        : "+f"(d[0]), "+f"(d[1]), "+f"(d[2]), "+f"(d[3]) \
        : "r"(a[0]), "r"(a[1]), "r"(a[2]), "r"(a[3]), "r"(b0_), "r"(b1_))
#define MMA_BF16(d, a, b0_, b1_) \
    asm volatile("mma.sync.aligned.m16n8k16.row.col.f32.bf16.bf16.f32 " \
        "{%0,%1,%2,%3},{%4,%5,%6,%7},{%8,%9},{%0,%1,%2,%3};" \
        : "+f"(d[0]), "+f"(d[1]), "+f"(d[2]), "+f"(d[3]) \
        : "r"(a[0]), "r"(a[1]), "r"(a[2]), "r"(a[3]), "r"(b0_), "r"(b1_))

__device__ __forceinline__ void bf8_to_f(const uint4& u, float* f) {
    const __nv_bfloat162* p = (const __nv_bfloat162*)&u;
#pragma unroll
    for (int j = 0; j < 4; j++) {
        float2 t = __bfloat1622float2(p[j]);
        f[2 * j] = t.x; f[2 * j + 1] = t.y;
    }
}
__device__ __forceinline__ uint4 f_to_bf8(const float* f) {
    uint4 u;
    __nv_bfloat162* p = (__nv_bfloat162*)&u;
#pragma unroll
    for (int j = 0; j < 4; j++)
        p[j] = __float22bfloat162_rn(make_float2(f[2 * j], f[2 * j + 1]));
    return u;
}
__device__ __forceinline__ void bn_scales(const double* sum, const double* sq,
                                          const float* gamma, const float* beta,
                                          double count, int c, float& sc, float& sh) {
    double s = sum[c], q = sq[c];
    double m = s / count;
    double var = q / count - m * m;
    sc = gamma[c] * rsqrtf((float)var + 1e-5f);
    sh = beta[c] - (float)m * sc;
}

// ------------------------- setup ----------------------------------------------
__global__ void k_zero() {
    int i = blockIdx.x * blockDim.x + threadIdx.x;
    if (i < NN) g_cnt[i] = 0;
    if (i < 4 * DD) { g_esum[i] = 0.0; g_esq[i] = 0.0; g_hsum[i] = 0.0; g_hsq[i] = 0.0; }
}

__global__ void k_prep(const float* __restrict__ h1, const float* __restrict__ h2,
                       const float* __restrict__ z,
                       const float* __restrict__ Wh, const float* __restrict__ bh,
                       const float* __restrict__ WA, const float* __restrict__ WB,
                       const float* __restrict__ WC, const float* __restrict__ WD,
                       const float* __restrict__ WE) {
    int t = threadIdx.x;
    if (blockIdx.x < EMB_BLKS) {
        __shared__ float Ws[26 * DD];
        for (int i = t; i < 26 * DD; i += 256) Ws[i] = Wh[i];
        __syncthreads();
        int idx = blockIdx.x * 256 + t;
        if (idx >= NN * DD) return;
        int r = idx / DD, c = idx - (idx / DD) * DD;
        float acc = bh[c];
#pragma unroll
        for (int k = 0; k < 6; k++)  acc += h1[r * 6 + k]  * Ws[k * DD + c];
#pragma unroll
        for (int k = 0; k < 4; k++)  acc += h2[r * 4 + k]  * Ws[(6 + k) * DD + c];
#pragma unroll
        for (int k = 0; k < 16; k++) acc += z[r * 16 + k]  * Ws[(10 + k) * DD + c];
        g_h[idx] = acc;
        return;
    }
    int j = (blockIdx.x - EMB_BLKS) * 256 + t;
    if (j < 73728) {
        int l = j / 18432, r = j - l * 18432;
        int k = r / 192, c = r - k * 192;
        int m = c / DD, cc = c - m * DD;
        const float* src = m ? WE : WD;
        g_WDE[j] = tf32r(src[(size_t)l * DD * DD + k * DD + cc]);
    } else if (j < 147456) {
        int i = j - 73728;
        int l = i / 18432, r = i - l * 18432;
        int k = r / 192, c = r - k * 192;
        int m = c / DD, cc = c - m * DD;
        const float* src = m ? WB : WA;
        g_WAB[i] = tf32r(src[(size_t)l * DD * DD + k * DD + cc]);
    } else if (j < 184320) {
        int i = j - 147456;
        int l = i / 9216, r = i - l * 9216;
        int k = r / DD, n = r - k * DD;
        g_WtC[l * DD * DD + n * DD + k] = __float2bfloat16(WC[(size_t)l * DD * DD + k * DD + n]);
    }
}

// ------------------------- CSR build ------------------------------------------
__global__ void k_count(const int* __restrict__ dst) {
    int i = blockIdx.x * blockDim.x + threadIdx.x;
    if (i < EE) atomicAdd(&g_cnt[dst[i]], 1);
}

__global__ void k_scan1() {
    __shared__ int sh[256];
    int t = threadIdx.x, b = blockIdx.x;
    int j = b * 256 + t;
    int v = (j < NN) ? g_cnt[j] : 0;
    sh[t] = v; __syncthreads();
    for (int off = 1; off < 256; off <<= 1) {
        int u = (t >= off) ? sh[t - off] : 0;
        __syncthreads();
        sh[t] += u;
        __syncthreads();
    }
    if (j < NN) g_ptr[j] = sh[t] - v;
    if (t == 255) g_bsum[b] = sh[t];
}

__global__ void k_scan2() {
    __shared__ int sh[256];
    int t = threadIdx.x;
    int v = (t < NBS) ? g_bsum[t] : 0;
    sh[t] = v; __syncthreads();
    for (int off = 1; off < 256; off <<= 1) {
        int u = (t >= off) ? sh[t - off] : 0;
        __syncthreads();
        sh[t] += u;
        __syncthreads();
    }
    g_boff[t] = sh[t] - v;
}

__global__ void k_scan3() {
    int j = blockIdx.x * blockDim.x + threadIdx.x;
    if (j < NN) {
        int p = g_ptr[j] + g_boff[j >> 8];
        g_ptr[j] = p; g_woff[j] = p;
    }
    if (j == 0) g_ptr[NN] = EE;
}

__global__ void k_fill(const int* __restrict__ dst) {
    int i = blockIdx.x * blockDim.x + threadIdx.x;
    if (i < EE) {
        int pos = atomicAdd(&g_woff[dst[i]], 1);
        g_eid[pos] = i;
    }
}

__global__ void k_sortperm(const int* __restrict__ src, const int* __restrict__ dst) {
    int v = blockIdx.x * blockDim.x + threadIdx.x;
    if (v >= NN) return;
    int lo = g_ptr[v], hi = g_ptr[v + 1];
    for (int i = lo + 1; i < hi; i++) {
        int key = g_eid[i]; int j = i - 1;
        while (j >= lo && g_eid[j] > key) { g_eid[j + 1] = g_eid[j]; j--; }
        g_eid[j + 1] = key;
    }
    for (int i = lo; i < hi; i++) {
        int ei = g_eid[i];
        g_srcp[i] = src[ei];
        g_dstp[i] = dst[ei];
    }
}

// ------------------------- node GEMM (tf32 MMA), 2-matrix variant -------------
__global__ __launch_bounds__(256) void k_mat2(const float* __restrict__ Wcat,
                                              const float* __restrict__ b0_,
                                              const float* __restrict__ b1_,
                                              const float* __restrict__ hg,
                                              const float* __restrict__ hbt,
                                              int layer, int apply, int isAB) {
    extern __shared__ float dyn[];
    float* Ws = dyn;
    float* Xs = dyn + DD * WS2;
    float* Bs = Xs + 64 * XSTR;
    __shared__ float shsc[DD], shsh[DD];
    int t = threadIdx.x;
    int lane = t & 31, w = t >> 5;
    if (apply && t < DD)
        bn_scales(g_hsum + (layer - 1) * DD, g_hsq + (layer - 1) * DD,
                  hg, hbt, (double)NN, t, shsc[t], shsh[t]);
    for (int i = t; i < DD * 48; i += 256) {
        int k = i / 48, c4 = (i - (i / 48) * 48) * 4;
        *(float4*)(Ws + k * WS2 + c4) = *(const float4*)(Wcat + k * 192 + c4);
    }
    for (int i = t; i < 192; i += 256) Bs[i] = (i < DD) ? b0_[i] : b1_[i - DD];
    __syncthreads();
    int row0 = blockIdx.x * 64;
    for (int i = t; i < 64 * 24; i += 256) {
        int r = i / 24, c4 = (i - (i / 24) * 24) * 4;
        int gr = row0 + r;
        float4 v = make_float4(0.f, 0.f, 0.f, 0.f);
        if (gr < NN) {
            size_t idx = (size_t)gr * DD + c4;
            v = *(const float4*)(g_h + idx);
            if (apply) {
                float4 en = *(const float4*)(g_hnew + idx);
                v.x += fmaxf(shsc[c4 + 0] * en.x + shsh[c4 + 0], 0.f);
                v.y += fmaxf(shsc[c4 + 1] * en.y + shsh[c4 + 1], 0.f);
                v.z += fmaxf(shsc[c4 + 2] * en.z + shsh[c4 + 2], 0.f);
                v.w += fmaxf(shsc[c4 + 3] * en.w + shsh[c4 + 3], 0.f);
                *(float4*)(g_h + idx) = v;
            }
        }
        v.x = tf32r(v.x); v.y = tf32r(v.y); v.z = tf32r(v.z); v.w = tf32r(v.w);
        *(float4*)(Xs + r * XSTR + c4) = v;
    }
    __syncthreads();

    int mg = w >> 2, ng = w & 3;
    int m0 = mg * 32, n0 = ng * 48;
    int g = lane >> 2, c4 = lane & 3;
    float acc[2][6][4];
#pragma unroll
    for (int i = 0; i < 2; i++)
#pragma unroll
        for (int j = 0; j < 6; j++)
#pragma unroll
            for (int q = 0; q < 4; q++) acc[i][j][q] = 0.f;

#pragma unroll
    for (int k0 = 0; k0 < DD; k0 += 8) {
        unsigned a[2][4];
#pragma unroll
        for (int i = 0; i < 2; i++) {
            int rr = (m0 + i * 16 + g) * XSTR;
            a[i][0] = __float_as_uint(Xs[rr + k0 + c4]);
            a[i][1] = __float_as_uint(Xs[rr + 8 * XSTR + k0 + c4]);
            a[i][2] = __float_as_uint(Xs[rr + k0 + 4 + c4]);
            a[i][3] = __float_as_uint(Xs[rr + 8 * XSTR + k0 + 4 + c4]);
        }
#pragma unroll
        for (int j = 0; j < 6; j++) {
            int col = n0 + 8 * j + g;
            unsigned b0 = __float_as_uint(Ws[(k0 + c4) * WS2 + col]);
            unsigned b1 = __float_as_uint(Ws[(k0 + 4 + c4) * WS2 + col]);
            MMA_TF32(acc[0][j], a[0], b0, b1);
            MMA_TF32(acc[1][j], a[1], b0, b1);
        }
    }

    int m = n0 / DD;
    int ncc = n0 - m * DD;
    __nv_bfloat16* outb = isAB ? g_B : (m == 0 ? g_D : g_E);
    int is_f32 = (isAB && m == 0);
#pragma unroll
    for (int i = 0; i < 2; i++) {
#pragma unroll
        for (int half = 0; half < 2; half++) {
            int rl = m0 + i * 16 + half * 8 + g;
            int gr = row0 + rl;
            if (gr < NN) {
#pragma unroll
                for (int j = 0; j < 6; j++) {
                    int col = n0 + 8 * j + 2 * c4;
                    int cc = ncc + 8 * j + 2 * c4;
                    float v0 = acc[i][j][half * 2 + 0] + Bs[col];
                    float v1 = acc[i][j][half * 2 + 1] + Bs[col + 1];
                    if (is_f32) {
                        *(float2*)(g_A + (size_t)gr * DD + cc) = make_float2(v0, v1);
                    } else {
                        *(__nv_bfloat162*)(outb + (size_t)gr * DD + cc) =
                            __float22bfloat162_rn(make_float2(v0, v1));
                    }
                }
            }
        }
    }
}

// ------------------------- edge kernel: 256 edges/block, bf16 MMA -------------
// 512 threads, 16 warps (8m x 2n), warp = 32x48. Dh staged; Eh direct (L1 hits).
__global__ __launch_bounds__(512) void k_edge(const __nv_bfloat16* __restrict__ Wtg,
                                              const float* __restrict__ b,
                                              const float* __restrict__ efeat,
                                              const float* __restrict__ Wemb,
                                              const float* __restrict__ bemb,
                                              const float* __restrict__ eg,
                                              const float* __restrict__ ebt,
                                              int layer, int embed, int apply,
                                              int write_e, int do_stats) {
    extern __shared__ char dync[];
    __nv_bfloat16* Wt = (__nv_bfloat16*)dync;        // [96 cols][WSTR]  (phase 1)
    __nv_bfloat16* Es = Wt + DD * WSTR;              // [256 rows][ESTRB] (phase 1)
    __nv_bfloat16* Ds = (__nv_bfloat16*)dync;        // [256][ESTRB] gathered Dh (phase 2)
    __shared__ float s_sum[DD], s_sq[DD], bsh[DD];
    __shared__ float s_esc[DD], s_esh[DD];
    __shared__ int s_src[ETILE], s_dst[ETILE];
    __shared__ float s_ef[ETILE * 4];
    __shared__ float s_wemb[4 * DD];
    __shared__ float s_bemb[DD];
    int t = threadIdx.x;
    int lane = t & 31, w = t >> 5;
    if (t < DD) {
        s_sum[t] = 0.f; s_sq[t] = 0.f; bsh[t] = b[t];
        if (apply)
            bn_scales(g_esum + (layer - 1) * DD, g_esq + (layer - 1) * DD,
                      eg, ebt, (double)EE, t, s_esc[t], s_esh[t]);
    }
    for (int i = t; i < DD * 12; i += 512) {
        int col = i / 12, kk = (i - (i / 12) * 12) * 8;
        *(uint4*)(Wt + col * WSTR + kk) = *(const uint4*)(Wtg + col * DD + kk);
    }
    int ebase = blockIdx.x * ETILE;   // EE % 256 == 0
    if (t < ETILE) { s_src[t] = g_srcp[ebase + t]; s_dst[t] = g_dstp[ebase + t]; }
    if (embed) {
        for (int i = t; i < 4 * DD; i += 512) s_wemb[i] = Wemb[i];
        if (t < DD) s_bemb[t] = bemb[t];
        if (t < ETILE) {
            int ei = g_eid[ebase + t];
            *(float4*)(s_ef + t * 4) = *(const float4*)(efeat + (size_t)ei * 4);
        }
    }
    __syncthreads();
    if (embed) {
        for (int i = t; i < ETILE * 12; i += 512) {
            int r = i / 12, c8 = (i - (i / 12) * 12) * 8;
            size_t idx = (size_t)(ebase + r) * DD + c8;
            float4 f = *(const float4*)(s_ef + r * 4);
            float v[8];
#pragma unroll
            for (int j = 0; j < 8; j++) {
                int c = c8 + j;
                v[j] = s_bemb[c] + f.x * s_wemb[c] + f.y * s_wemb[DD + c]
                     + f.z * s_wemb[2 * DD + c] + f.w * s_wemb[3 * DD + c];
            }
            uint4 packed = f_to_bf8(v);
            *(uint4*)(g_e + idx) = packed;
            *(uint4*)(Es + r * ESTRB + c8) = packed;
        }
    } else {
        for (int i = t; i < ETILE * 12; i += 512) {
            int r = i / 12, c8 = (i - (i / 12) * 12) * 8;
            size_t idx = (size_t)(ebase + r) * DD + c8;
            uint4 ue = *(const uint4*)(g_e + idx);
            if (apply) {
                float v[8], en[8];
                bf8_to_f(ue, v);
                uint4 un = *(const uint4*)(g_enew + idx);
                bf8_to_f(un, en);
#pragma unroll
                for (int j = 0; j < 8; j++)
                    v[j] += fmaxf(s_esc[c8 + j] * en[j] + s_esh[c8 + j], 0.f);
                uint4 packed = f_to_bf8(v);
                if (write_e) *(uint4*)(g_e + idx) = packed;
                *(uint4*)(Es + r * ESTRB + c8) = packed;
            } else {
                *(uint4*)(Es + r * ESTRB + c8) = ue;
            }
        }
    }
    __syncthreads();

    int mg = w >> 1, ng = w & 1;          // 8m x 2n
    int m0 = mg * 32, n0 = ng * 48;
    int g = lane >> 2, c4 = lane & 3;
    float acc[2][6][4];
#pragma unroll
    for (int i = 0; i < 2; i++)
#pragma unroll
        for (int j = 0; j < 6; j++)
#pragma unroll
            for (int q = 0; q < 4; q++) acc[i][j][q] = 0.f;

#pragma unroll
    for (int k0 = 0; k0 < DD; k0 += 16) {
        unsigned a[2][4];
#pragma unroll
        for (int i = 0; i < 2; i++) {
            int rr = (m0 + i * 16 + g) * ESTRB;
            a[i][0] = *(const unsigned*)(Es + rr + k0 + 2 * c4);
            a[i][1] = *(const unsigned*)(Es + rr + 8 * ESTRB + k0 + 2 * c4);
            a[i][2] = *(const unsigned*)(Es + rr + k0 + 8 + 2 * c4);
            a[i][3] = *(const unsigned*)(Es + rr + 8 * ESTRB + k0 + 8 + 2 * c4);
        }
#pragma unroll
        for (int j = 0; j < 6; j++) {
            int col = n0 + 8 * j + g;
            unsigned b0 = *(const unsigned*)(Wt + col * WSTR + k0 + 2 * c4);
            unsigned b1 = *(const unsigned*)(Wt + col * WSTR + k0 + 8 + 2 * c4);
            MMA_BF16(acc[0][j], a[0], b0, b1);
            MMA_BF16(acc[1][j], a[1], b0, b1);
        }
    }
    __syncthreads();   // Wt/Es dead; recycle smem for Dh rows

    for (int i = t; i < ETILE * 12; i += 512) {
        int r = i / 12, c8 = (i - (i / 12) * 12) * 8;
        *(uint4*)(Ds + r * ESTRB + c8) =
            *(const uint4*)(g_D + (size_t)s_src[r] * DD + c8);
    }
    __syncthreads();

    float cs[6][2], cq[6][2];
#pragma unroll
    for (int j = 0; j < 6; j++) { cs[j][0] = cs[j][1] = 0.f; cq[j][0] = cq[j][1] = 0.f; }
#pragma unroll
    for (int i = 0; i < 2; i++) {
#pragma unroll
        for (int half = 0; half < 2; half++) {
            int rl = m0 + i * 16 + half * 8 + g;
            size_t db = (size_t)s_dst[rl] * DD;
            size_t ob = (size_t)(ebase + rl) * DD;
#pragma unroll
            for (int j = 0; j < 6; j++) {
                int col = n0 + 8 * j + 2 * c4;
                float2 dh = __bfloat1622float2(*(const __nv_bfloat162*)(Ds + rl * ESTRB + col));
                float2 eh = __bfloat1622float2(*(const __nv_bfloat162*)(g_E + db + col));
                float v0 = acc[i][j][half * 2 + 0] + bsh[col]     + dh.x + eh.x;
                float v1 = acc[i][j][half * 2 + 1] + bsh[col + 1] + dh.y + eh.y;
                *(__nv_bfloat162*)(g_enew + ob + col) =
                    __float22bfloat162_rn(make_float2(v0, v1));
                cs[j][0] += v0; cs[j][1] += v1;
                cq[j][0] += v0 * v0; cq[j][1] += v1 * v1;
            }
        }
    }
    if (do_stats) {
#pragma unroll
        for (int off = 16; off >= 4; off >>= 1) {
#pragma unroll
            for (int j = 0; j < 6; j++) {
#pragma unroll
                for (int p = 0; p < 2; p++) {
                    cs[j][p] += __shfl_down_sync(0xffffffffu, cs[j][p], off);
                    cq[j][p] += __shfl_down_sync(0xffffffffu, cq[j][p], off);
                }
            }
        }
        if (lane < 4) {
#pragma unroll
            for (int j = 0; j < 6; j++) {
#pragma unroll
                for (int p = 0; p < 2; p++) {
                    int col = n0 + 8 * j + 2 * lane + p;
                    atomicAdd(&s_sum[col], cs[j][p]);
                    atomicAdd(&s_sq[col], cq[j][p]);
                }
            }
        }
        __syncthreads();
        if (t < DD) {
            atomicAdd(&g_esum[layer * DD + t], (double)s_sum[t]);
            atomicAdd(&g_esq[layer * DD + t], (double)s_sq[t]);
        }
    }
}

// ------------------------- aggregation (CSR, unroll x2) -----------------------
__global__ __launch_bounds__(256) void k_agg(int layer) {
    __shared__ float ssum[DD], ssq[DD];
    int t = threadIdx.x;
    if (t < DD) { ssum[t] = 0.f; ssq[t] = 0.f; }
    __syncthreads();
    int w = t >> 5, ln = t & 31;
    int v = blockIdx.x * 8 + w;
    float n0 = 0, n1 = 0, n2 = 0, d0 = 0, d1 = 0, d2 = 0;
    int p0 = g_ptr[v], p1 = g_ptr[v + 1];
    int p = p0;
    for (; p + 1 < p1; p += 2) {
        int sa = g_srcp[p], sb_ = g_srcp[p + 1];
        size_t ea = (size_t)p * DD, eb = (size_t)(p + 1) * DD;
        size_t sba = (size_t)sa * DD, sbb = (size_t)sb_ * DD;
        float xa0 = __bfloat162float(g_enew[ea + ln]);
        float xa1 = __bfloat162float(g_enew[ea + ln + 32]);
        float xa2 = __bfloat162float(g_enew[ea + ln + 64]);
        float xb0 = __bfloat162float(g_enew[eb + ln]);
        float xb1 = __bfloat162float(g_enew[eb + ln + 32]);
        float xb2 = __bfloat162float(g_enew[eb + ln + 64]);
        float ba0 = __bfloat162float(g_B[sba + ln]);
        float ba1 = __bfloat162float(g_B[sba + ln + 32]);
        float ba2 = __bfloat162float(g_B[sba + ln + 64]);
        float bb0 = __bfloat162float(g_B[sbb + ln]);
        float bb1 = __bfloat162float(g_B[sbb + ln + 32]);
        float bb2 = __bfloat162float(g_B[sbb + ln + 64]);
        float sa0 = __fdividef(1.f, 1.f + __expf(-xa0));
        float sa1 = __fdividef(1.f, 1.f + __expf(-xa1));
        float sa2 = __fdividef(1.f, 1.f + __expf(-xa2));
        float sb0 = __fdividef(1.f, 1.f + __expf(-xb0));
        float sb1 = __fdividef(1.f, 1.f + __expf(-xb1));
        float sb2 = __fdividef(1.f, 1.f + __expf(-xb2));
        n0 += sa0 * ba0; n0 += sb0 * bb0;
        n1 += sa1 * ba1; n1 += sb1 * bb1;
        n2 += sa2 * ba2; n2 += sb2 * bb2;
        d0 += sa0; d0 += sb0;
        d1 += sa1; d1 += sb1;
        d2 += sa2; d2 += sb2;
    }
    if (p < p1) {
        int s = g_srcp[p];
        size_t eb = (size_t)p * DD;
        size_t sb = (size_t)s * DD;
        float x0 = __bfloat162float(g_enew[eb + ln]);
        float x1 = __bfloat162float(g_enew[eb + ln + 32]);
        float x2 = __bfloat162float(g_enew[eb + ln + 64]);
        float s0 = __fdividef(1.f, 1.f + __expf(-x0));
        float s1 = __fdividef(1.f, 1.f + __expf(-x1));
        float s2 = __fdividef(1.f, 1.f + __expf(-x2));
        n0 += s0 * __bfloat162float(g_B[sb + ln]);
        n1 += s1 * __bfloat162float(g_B[sb + ln + 32]);
        n2 += s2 * __bfloat162float(g_B[sb + ln + 64]);
        d0 += s0; d1 += s1; d2 += s2;
    }
    size_t vb = (size_t)v * DD;
    float h0 = g_A[vb + ln]      + __fdividef(n0, d0 + 1e-6f);
    float h1 = g_A[vb + ln + 32] + __fdividef(n1, d1 + 1e-6f);
    float h2 = g_A[vb + ln + 64] + __fdividef(n2, d2 + 1e-6f);
    g_hnew[vb + ln] = h0; g_hnew[vb + ln + 32] = h1; g_hnew[vb + ln + 64] = h2;
    atomicAdd(&ssum[ln], h0);      atomicAdd(&ssum[ln + 32], h1); atomicAdd(&ssum[ln + 64], h2);
    atomicAdd(&ssq[ln], h0 * h0);  atomicAdd(&ssq[ln + 32], h1 * h1); atomicAdd(&ssq[ln + 64], h2 * h2);
    __syncthreads();
    if (t < DD) {
        atomicAdd(&g_hsum[layer * DD + t], (double)ssum[t]);
        atomicAdd(&g_hsq[layer * DD + t], (double)ssq[t]);
    }
}

// ------------------------- head -----------------------------------------------
__global__ __launch_bounds__(256) void k_head(const float* __restrict__ W1,
                                              const float* __restrict__ b1,
                                              const float* __restrict__ W2,
                                              const float* __restrict__ b2,
                                              const float* __restrict__ maxa,
                                              const float* __restrict__ hg,
                                              const float* __restrict__ hbt,
                                              float* __restrict__ out) {
    extern __shared__ float dyn[];
    float* W1s = dyn;
    float* Hs  = W1s + DD * HIDN;
    float* His = Hs + 32 * DD;
    float* W2s = His + 32 * 132;
    __shared__ float hsc[DD], hsh[DD];
    int t = threadIdx.x;
    if (t < DD)
        bn_scales(g_hsum + 3 * DD, g_hsq + 3 * DD, hg, hbt, (double)NN, t, hsc[t], hsh[t]);
    for (int i = t; i < DD * HIDN; i += 256) W1s[i] = W1[i];
    for (int i = t; i < HIDN * OUTN; i += 256) W2s[i] = W2[i];
    __syncthreads();
    int row0 = blockIdx.x * 32;
    for (int i = t; i < 32 * 24; i += 256) {
        int r = i / 24, c4 = (i - (i / 24) * 24) * 4;
        int gr = row0 + r;
        float4 v = make_float4(0.f, 0.f, 0.f, 0.f);
        if (gr < NN) {
            size_t idx = (size_t)gr * DD + c4;
            v = *(const float4*)(g_h + idx);
            float4 en = *(const float4*)(g_hnew + idx);
            v.x += fmaxf(hsc[c4 + 0] * en.x + hsh[c4 + 0], 0.f);
            v.y += fmaxf(hsc[c4 + 1] * en.y + hsh[c4 + 1], 0.f);
            v.z += fmaxf(hsc[c4 + 2] * en.z + hsh[c4 + 2], 0.f);
            v.w += fmaxf(hsc[c4 + 3] * en.w + hsh[c4 + 3], 0.f);
        }
        *(float4*)(Hs + r * DD + c4) = v;
    }
    __syncthreads();
    {
        int ng = t >> 5, hgr = t & 31;
        int r0 = ng * 4, c0 = hgr * 4;
        ull acc[4][2];
        float4 bv = *(const float4*)(b1 + c0);
        ull b01 = pk2(bv.x, bv.y), b23 = pk2(bv.z, bv.w);
#pragma unroll
        for (int r = 0; r < 4; r++) { acc[r][0] = b01; acc[r][1] = b23; }
#pragma unroll 4
        for (int k = 0; k < DD; k++) {
            ulonglong2 wv = *(const ulonglong2*)(W1s + k * HIDN + c0);
#pragma unroll
            for (int r = 0; r < 4; r++) {
                float x = Hs[(r0 + r) * DD + k];
                ull xx = pk2(x, x);
                acc[r][0] = fma2(xx, wv.x, acc[r][0]);
                acc[r][1] = fma2(xx, wv.y, acc[r][1]);
            }
        }
#pragma unroll
        for (int r = 0; r < 4; r++) {
            float2 a = upk(acc[r][0]), q = upk(acc[r][1]);
            His[(r0 + r) * 132 + c0 + 0] = fmaxf(a.x, 0.f);
            His[(r0 + r) * 132 + c0 + 1] = fmaxf(a.y, 0.f);
            His[(r0 + r) * 132 + c0 + 2] = fmaxf(q.x, 0.f);
            His[(r0 + r) * 132 + c0 + 3] = fmaxf(q.y, 0.f);
        }
    }
    __syncthreads();
    {
        int node = t >> 3, oc = t & 7;
        int gn = row0 + node;
        if (gn < NN) {
            float acc = b2[oc];
#pragma unroll 8
            for (int k = 0; k < HIDN; k++) acc += His[node * 132 + k] * W2s[k * OUTN + oc];
            out[(size_t)gn * OUTN + oc] = maxa[gn] * tanhf(acc);
        }
    }
}

// ------------------------- launch ---------------------------------------------
extern "C" void kernel_launch(void* const* d_in, const int* in_sizes, int n_in,
                              void* d_out, int out_size) {
    const float* h1      = (const float*)d_in[0];
    const float* h2      = (const float*)d_in[1];
    const float* z       = (const float*)d_in[2];
    const float* efeat   = (const float*)d_in[3];
    const float* maxa    = (const float*)d_in[4];
    const float* Wh_emb  = (const float*)d_in[5];
    const float* bh_emb  = (const float*)d_in[6];
    const float* We_emb  = (const float*)d_in[7];
    const float* be_emb  = (const float*)d_in[8];
    const float* WA      = (const float*)d_in[9];
    const float* bA      = (const float*)d_in[10];
    const float* WB      = (const float*)d_in[11];
    const float* bB      = (const float*)d_in[12];
    const float* WC      = (const float*)d_in[13];
    const float* bC      = (const float*)d_in[14];
    const float* WD      = (const float*)d_in[15];
    const float* bD      = (const float*)d_in[16];
    const float* WE      = (const float*)d_in[17];
    const float* bE      = (const float*)d_in[18];
    const float* bn_h_g  = (const float*)d_in[19];
    const float* bn_h_b  = (const float*)d_in[20];
    const float* bn_e_g  = (const float*)d_in[21];
    const float* bn_e_b  = (const float*)d_in[22];
    const float* W1      = (const float*)d_in[23];
    const float* b1      = (const float*)d_in[24];
    const float* W2      = (const float*)d_in[25];
    const float* b2      = (const float*)d_in[26];
    const int*   src     = (const int*)d_in[27];
    const int*   dst     = (const int*)d_in[28];
    float* out = (float*)d_out;

    static cudaStream_t s1 = nullptr;
    static cudaEvent_t ev0, evCSR, evDE[4], evAB[4];
    if (!s1) {
        cudaStreamCreateWithFlags(&s1, cudaStreamNonBlocking);
        cudaEventCreateWithFlags(&ev0, cudaEventDisableTiming);
        cudaEventCreateWithFlags(&evCSR, cudaEventDisableTiming);
        for (int i = 0; i < 4; i++) {
            cudaEventCreateWithFlags(&evDE[i], cudaEventDisableTiming);
            cudaEventCreateWithFlags(&evAB[i], cudaEventDisableTiming);
        }
    }

    float *WDE_base, *WAB_base;
    __nv_bfloat16* WtC_base;
    cudaGetSymbolAddress((void**)&WDE_base, g_WDE);
    cudaGetSymbolAddress((void**)&WAB_base, g_WAB);
    cudaGetSymbolAddress((void**)&WtC_base, g_WtC);

    cudaFuncSetAttribute(k_mat2, cudaFuncAttributeMaxDynamicSharedMemorySize, 110 * 1024);
    cudaFuncSetAttribute(k_edge, cudaFuncAttributeMaxDynamicSharedMemorySize, 96 * 1024);
    cudaFuncSetAttribute(k_head, cudaFuncAttributeMaxDynamicSharedMemorySize, 96 * 1024);

    const int smem_mat2 = (DD * WS2 + 64 * XSTR + 192) * 4;                     // 105216
    const int smem_edge = (DD * WSTR + ETILE * ESTRB) * 2;                      // 73216
    const int smem_head = (DD * HIDN + 32 * DD + 32 * 132 + HIDN * OUTN) * 4;   // 82432

    k_zero<<<(NN + 255) / 256, 256>>>();
    cudaEventRecord(ev0, 0);
    cudaStreamWaitEvent(s1, ev0, 0);
    k_count<<<EE / 256, 256, 0, s1>>>(dst);
    k_scan1<<<NBS, 256, 0, s1>>>();
    k_scan2<<<1, 256, 0, s1>>>();
    k_scan3<<<NBS, 256, 0, s1>>>();
    k_fill<<<EE / 256, 256, 0, s1>>>(dst);
    k_sortperm<<<(NN + 127) / 128, 128, 0, s1>>>(src, dst);
    cudaEventRecord(evCSR, s1);

    const int prep_blks = EMB_BLKS + (184320 + 255) / 256;
    k_prep<<<prep_blks, 256>>>(h1, h2, z, Wh_emb, bh_emb, WA, WB, WC, WD, WE);

    const int ablk = (NN + 63) / 64;   // 782
    const int eblk = EE / ETILE;       // 3125

    for (int l = 0; l < 4; l++) {
        int lp = (l > 0) ? l - 1 : 0;
        k_mat2<<<ablk, 256, smem_mat2>>>(WDE_base + l * DD * 192,
                                         bD + l * DD, bE + l * DD,
                                         bn_h_g + lp * DD, bn_h_b + lp * DD,
                                         l, l >= 1 ? 1 : 0, 0);
        cudaEventRecord(evDE[l], 0);
        cudaStreamWaitEvent(s1, evDE[l], 0);
        k_mat2<<<ablk, 256, smem_mat2, s1>>>(WAB_base + l * DD * 192,
                                             bA + l * DD, bB + l * DD,
                                             bn_h_g, bn_h_b, l, 0, 1);
        cudaEventRecord(evAB[l], s1);

        if (l == 0) cudaStreamWaitEvent(0, evCSR, 0);
        int embed = (l == 0) ? 1 : 0;
        int apply = (l >= 1) ? 1 : 0;
        int write_e = (l >= 1 && l < 3) ? 1 : 0;
        int do_stats = (l < 3) ? 1 : 0;
        k_edge<<<eblk, 512, smem_edge>>>(WtC_base + l * DD * DD, bC + l * DD,
                                         efeat, We_emb, be_emb,
                                         bn_e_g + lp * DD, bn_e_b + lp * DD,
                                         l, embed, apply, write_e, do_stats);

        cudaStreamWaitEvent(0, evAB[l], 0);
        k_agg<<<NN / 8, 256>>>(l);
    }

    k_head<<<(NN + 31) / 32, 256, smem_head>>>(W1, b1, W2, b2, maxa,
                                               bn_h_g + 3 * DD, bn_h_b + 3 * DD, out);
}

// round 15
// speedup vs baseline: 1.1881x; 1.1881x over previous
#include <cuda_runtime.h>
#include <cuda_bf16.h>
#include <math.h>

#define NN 50000
#define EE 800000
#define DD 96
#define HIDN 128
#define OUTN 8
#define NBS 196    // scan blocks = ceil(NN/256)
#define WSTR 104   // bf16 smem stride (elements) for W^T  — conflict-free (edge)
#define ESTRB 104  // bf16 smem stride (elements) for E tile (edge)
#define XSTR 108   // f32/tf32 smem stride for X tile (mat kernels)
#define WS2 200    // f32/tf32 smem stride for 2-matrix concat W (mat kernels)
#define EMB_BLKS 18750  // (NN*DD+255)/256

typedef unsigned long long ull;

// ------------------------- device scratch (no allocs allowed) ----------------
__device__ float g_h[(size_t)NN * DD];
__device__ float g_hnew[(size_t)NN * DD];
__device__ float g_A[(size_t)NN * DD];             // f32 (residual-critical)
__device__ __nv_bfloat16 g_B[(size_t)NN * DD];     // gathered tables in bf16
__device__ __nv_bfloat16 g_D[(size_t)NN * DD];
__device__ __nv_bfloat16 g_E[(size_t)NN * DD];
__device__ __nv_bfloat16 g_e[(size_t)EE * DD];     // permuted (CSR dst order)
__device__ __nv_bfloat16 g_enew[(size_t)EE * DD];  // permuted
__device__ __nv_bfloat16 g_WtC[4 * DD * DD];       // pre-transposed bf16 WC per layer
__device__ float g_WDE[4 * DD * 192];              // tf32-prerounded [WD|WE] per layer
__device__ float g_WAB[4 * DD * 192];              // tf32-prerounded [WA|WB] per layer
__device__ int   g_cnt[NN];
__device__ int   g_ptr[NN + 1];
__device__ int   g_woff[NN];
__device__ int   g_eid[EE];
__device__ int   g_srcp[EE];
__device__ int   g_dstp[EE];
__device__ int   g_bsum[256];
__device__ int   g_boff[256];
// layer-indexed stats (no reset races)
__device__ double g_esum[4 * DD], g_esq[4 * DD], g_hsum[4 * DD], g_hsq[4 * DD];

// ------------------------- helpers -------------------------------------------
__device__ __forceinline__ ull pk2(float lo, float hi) {
    ull r; asm("mov.b64 %0,{%1,%2};" : "=l"(r) : "f"(lo), "f"(hi)); return r;
}
__device__ __forceinline__ ull fma2(ull a, ull b, ull c) {
    ull d; asm("fma.rn.f32x2 %0,%1,%2,%3;" : "=l"(d) : "l"(a), "l"(b), "l"(c)); return d;
}
__device__ __forceinline__ float2 upk(ull v) {
    float2 f; asm("mov.b64 {%0,%1},%2;" : "=f"(f.x), "=f"(f.y) : "l"(v)); return f;
}
__device__ __forceinline__ float tf32r(float x) {
    unsigned u; asm("cvt.rna.tf32.f32 %0,%1;" : "=r"(u) : "f"(x));
    return __uint_as_float(u);
}
#define MMA_TF32(d, a, b0_, b1_) \
    asm volatile("mma.sync.aligned.m16n8k8.row.col.f32.tf32.tf32.f32 " \
        "{%0,%1,%2,%3},{%4,%5,%6,%7},{%8,%9},{%0,%1,%2,%3};" \
        : "+f"(d[0]), "+f"(d[1]), "+f"(d[2]), "+f"(d[3]) \
        : "r"(a[0]), "r"(a[1]), "r"(a[2]), "r"(a[3]), "r"(b0_), "r"(b1_))
#define MMA_BF16(d, a, b0_, b1_) \
    asm volatile("mma.sync.aligned.m16n8k16.row.col.f32.bf16.bf16.f32 " \
        "{%0,%1,%2,%3},{%4,%5,%6,%7},{%8,%9},{%0,%1,%2,%3};" \
        : "+f"(d[0]), "+f"(d[1]), "+f"(d[2]), "+f"(d[3]) \
        : "r"(a[0]), "r"(a[1]), "r"(a[2]), "r"(a[3]), "r"(b0_), "r"(b1_))

__device__ __forceinline__ void bf8_to_f(const uint4& u, float* f) {
    const __nv_bfloat162* p = (const __nv_bfloat162*)&u;
#pragma unroll
    for (int j = 0; j < 4; j++) {
        float2 t = __bfloat1622float2(p[j]);
        f[2 * j] = t.x; f[2 * j + 1] = t.y;
    }
}
__device__ __forceinline__ uint4 f_to_bf8(const float* f) {
    uint4 u;
    __nv_bfloat162* p = (__nv_bfloat162*)&u;
#pragma unroll
    for (int j = 0; j < 4; j++)
        p[j] = __float22bfloat162_rn(make_float2(f[2 * j], f[2 * j + 1]));
    return u;
}
__device__ __forceinline__ void bn_scales(const double* sum, const double* sq,
                                          const float* gamma, const float* beta,
                                          double count, int c, float& sc, float& sh) {
    double s = sum[c], q = sq[c];
    double m = s / count;
    double var = q / count - m * m;
    sc = gamma[c] * rsqrtf((float)var + 1e-5f);
    sh = beta[c] - (float)m * sc;
}

// ------------------------- setup ----------------------------------------------
__global__ void k_zero() {
    int i = blockIdx.x * blockDim.x + threadIdx.x;
    if (i < NN) g_cnt[i] = 0;
    if (i < 4 * DD) { g_esum[i] = 0.0; g_esq[i] = 0.0; g_hsum[i] = 0.0; g_hsq[i] = 0.0; }
}

__global__ void k_prep(const float* __restrict__ h1, const float* __restrict__ h2,
                       const float* __restrict__ z,
                       const float* __restrict__ Wh, const float* __restrict__ bh,
                       const float* __restrict__ WA, const float* __restrict__ WB,
                       const float* __restrict__ WC, const float* __restrict__ WD,
                       const float* __restrict__ WE) {
    int t = threadIdx.x;
    if (blockIdx.x < EMB_BLKS) {
        __shared__ float Ws[26 * DD];
        for (int i = t; i < 26 * DD; i += 256) Ws[i] = Wh[i];
        __syncthreads();
        int idx = blockIdx.x * 256 + t;
        if (idx >= NN * DD) return;
        int r = idx / DD, c = idx - (idx / DD) * DD;
        float acc = bh[c];
#pragma unroll
        for (int k = 0; k < 6; k++)  acc += h1[r * 6 + k]  * Ws[k * DD + c];
#pragma unroll
        for (int k = 0; k < 4; k++)  acc += h2[r * 4 + k]  * Ws[(6 + k) * DD + c];
#pragma unroll
        for (int k = 0; k < 16; k++) acc += z[r * 16 + k]  * Ws[(10 + k) * DD + c];
        g_h[idx] = acc;
        return;
    }
    int j = (blockIdx.x - EMB_BLKS) * 256 + t;
    if (j < 73728) {
        int l = j / 18432, r = j - l * 18432;
        int k = r / 192, c = r - k * 192;
        int m = c / DD, cc = c - m * DD;
        const float* src = m ? WE : WD;
        g_WDE[j] = tf32r(src[(size_t)l * DD * DD + k * DD + cc]);
    } else if (j < 147456) {
        int i = j - 73728;
        int l = i / 18432, r = i - l * 18432;
        int k = r / 192, c = r - k * 192;
        int m = c / DD, cc = c - m * DD;
        const float* src = m ? WB : WA;
        g_WAB[i] = tf32r(src[(size_t)l * DD * DD + k * DD + cc]);
    } else if (j < 184320) {
        int i = j - 147456;
        int l = i / 9216, r = i - l * 9216;
        int k = r / DD, n = r - k * DD;
        g_WtC[l * DD * DD + n * DD + k] = __float2bfloat16(WC[(size_t)l * DD * DD + k * DD + n]);
    }
}

// ------------------------- CSR build ------------------------------------------
__global__ void k_count(const int* __restrict__ dst) {
    int i = blockIdx.x * blockDim.x + threadIdx.x;
    if (i < EE) atomicAdd(&g_cnt[dst[i]], 1);
}

__global__ void k_scan1() {
    __shared__ int sh[256];
    int t = threadIdx.x, b = blockIdx.x;
    int j = b * 256 + t;
    int v = (j < NN) ? g_cnt[j] : 0;
    sh[t] = v; __syncthreads();
    for (int off = 1; off < 256; off <<= 1) {
        int u = (t >= off) ? sh[t - off] : 0;
        __syncthreads();
        sh[t] += u;
        __syncthreads();
    }
    if (j < NN) g_ptr[j] = sh[t] - v;
    if (t == 255) g_bsum[b] = sh[t];
}

__global__ void k_scan2() {
    __shared__ int sh[256];
    int t = threadIdx.x;
    int v = (t < NBS) ? g_bsum[t] : 0;
    sh[t] = v; __syncthreads();
    for (int off = 1; off < 256; off <<= 1) {
        int u = (t >= off) ? sh[t - off] : 0;
        __syncthreads();
        sh[t] += u;
        __syncthreads();
    }
    g_boff[t] = sh[t] - v;
}

__global__ void k_scan3() {
    int j = blockIdx.x * blockDim.x + threadIdx.x;
    if (j < NN) {
        int p = g_ptr[j] + g_boff[j >> 8];
        g_ptr[j] = p; g_woff[j] = p;
    }
    if (j == 0) g_ptr[NN] = EE;
}

__global__ void k_fill(const int* __restrict__ dst) {
    int i = blockIdx.x * blockDim.x + threadIdx.x;
    if (i < EE) {
        int pos = atomicAdd(&g_woff[dst[i]], 1);
        g_eid[pos] = i;
    }
}

__global__ void k_sortperm(const int* __restrict__ src, const int* __restrict__ dst) {
    int v = blockIdx.x * blockDim.x + threadIdx.x;
    if (v >= NN) return;
    int lo = g_ptr[v], hi = g_ptr[v + 1];
    for (int i = lo + 1; i < hi; i++) {
        int key = g_eid[i]; int j = i - 1;
        while (j >= lo && g_eid[j] > key) { g_eid[j + 1] = g_eid[j]; j--; }
        g_eid[j + 1] = key;
    }
    for (int i = lo; i < hi; i++) {
        int ei = g_eid[i];
        g_srcp[i] = src[ei];
        g_dstp[i] = dst[ei];
    }
}

// ------------------------- node GEMM (tf32 MMA), 2-matrix variant -------------
__global__ __launch_bounds__(256) void k_mat2(const float* __restrict__ Wcat,
                                              const float* __restrict__ b0_,
                                              const float* __restrict__ b1_,
                                              const float* __restrict__ hg,
                                              const float* __restrict__ hbt,
                                              int layer, int apply, int isAB) {
    extern __shared__ float dyn[];
    float* Ws = dyn;
    float* Xs = dyn + DD * WS2;
    float* Bs = Xs + 64 * XSTR;
    __shared__ float shsc[DD], shsh[DD];
    int t = threadIdx.x;
    int lane = t & 31, w = t >> 5;
    if (apply && t < DD)
        bn_scales(g_hsum + (layer - 1) * DD, g_hsq + (layer - 1) * DD,
                  hg, hbt, (double)NN, t, shsc[t], shsh[t]);
    for (int i = t; i < DD * 48; i += 256) {
        int k = i / 48, c4 = (i - (i / 48) * 48) * 4;
        *(float4*)(Ws + k * WS2 + c4) = *(const float4*)(Wcat + k * 192 + c4);
    }
    for (int i = t; i < 192; i += 256) Bs[i] = (i < DD) ? b0_[i] : b1_[i - DD];
    __syncthreads();
    int row0 = blockIdx.x * 64;
    for (int i = t; i < 64 * 24; i += 256) {
        int r = i / 24, c4 = (i - (i / 24) * 24) * 4;
        int gr = row0 + r;
        float4 v = make_float4(0.f, 0.f, 0.f, 0.f);
        if (gr < NN) {
            size_t idx = (size_t)gr * DD + c4;
            v = *(const float4*)(g_h + idx);
            if (apply) {
                float4 en = *(const float4*)(g_hnew + idx);
                v.x += fmaxf(shsc[c4 + 0] * en.x + shsh[c4 + 0], 0.f);
                v.y += fmaxf(shsc[c4 + 1] * en.y + shsh[c4 + 1], 0.f);
                v.z += fmaxf(shsc[c4 + 2] * en.z + shsh[c4 + 2], 0.f);
                v.w += fmaxf(shsc[c4 + 3] * en.w + shsh[c4 + 3], 0.f);
                *(float4*)(g_h + idx) = v;
            }
        }
        v.x = tf32r(v.x); v.y = tf32r(v.y); v.z = tf32r(v.z); v.w = tf32r(v.w);
        *(float4*)(Xs + r * XSTR + c4) = v;
    }
    __syncthreads();

    int mg = w >> 2, ng = w & 3;
    int m0 = mg * 32, n0 = ng * 48;
    int g = lane >> 2, c4 = lane & 3;
    float acc[2][6][4];
#pragma unroll
    for (int i = 0; i < 2; i++)
#pragma unroll
        for (int j = 0; j < 6; j++)
#pragma unroll
            for (int q = 0; q < 4; q++) acc[i][j][q] = 0.f;

#pragma unroll
    for (int k0 = 0; k0 < DD; k0 += 8) {
        unsigned a[2][4];
#pragma unroll
        for (int i = 0; i < 2; i++) {
            int rr = (m0 + i * 16 + g) * XSTR;
            a[i][0] = __float_as_uint(Xs[rr + k0 + c4]);
            a[i][1] = __float_as_uint(Xs[rr + 8 * XSTR + k0 + c4]);
            a[i][2] = __float_as_uint(Xs[rr + k0 + 4 + c4]);
            a[i][3] = __float_as_uint(Xs[rr + 8 * XSTR + k0 + 4 + c4]);
        }
#pragma unroll
        for (int j = 0; j < 6; j++) {
            int col = n0 + 8 * j + g;
            unsigned b0 = __float_as_uint(Ws[(k0 + c4) * WS2 + col]);
            unsigned b1 = __float_as_uint(Ws[(k0 + 4 + c4) * WS2 + col]);
            MMA_TF32(acc[0][j], a[0], b0, b1);
            MMA_TF32(acc[1][j], a[1], b0, b1);
        }
    }

    int m = n0 / DD;
    int ncc = n0 - m * DD;
    __nv_bfloat16* outb = isAB ? g_B : (m == 0 ? g_D : g_E);
    int is_f32 = (isAB && m == 0);
#pragma unroll
    for (int i = 0; i < 2; i++) {
#pragma unroll
        for (int half = 0; half < 2; half++) {
            int rl = m0 + i * 16 + half * 8 + g;
            int gr = row0 + rl;
            if (gr < NN) {
#pragma unroll
                for (int j = 0; j < 6; j++) {
                    int col = n0 + 8 * j + 2 * c4;
                    int cc = ncc + 8 * j + 2 * c4;
                    float v0 = acc[i][j][half * 2 + 0] + Bs[col];
                    float v1 = acc[i][j][half * 2 + 1] + Bs[col + 1];
                    if (is_f32) {
                        *(float2*)(g_A + (size_t)gr * DD + cc) = make_float2(v0, v1);
                    } else {
                        *(__nv_bfloat162*)(outb + (size_t)gr * DD + cc) =
                            __float22bfloat162_rn(make_float2(v0, v1));
                    }
                }
            }
        }
    }
}

// ------------------------- edge kernel: 128 edges/block, bf16 MMA -------------
// (R13 winning shape; phase 2 stages only Dh — Eh reads are L1 hits.)
__global__ __launch_bounds__(256) void k_edge(const __nv_bfloat16* __restrict__ Wtg,
                                              const float* __restrict__ b,
                                              const float* __restrict__ efeat,
                                              const float* __restrict__ Wemb,
                                              const float* __restrict__ bemb,
                                              const float* __restrict__ eg,
                                              const float* __restrict__ ebt,
                                              int layer, int embed, int apply,
                                              int write_e, int do_stats) {
    extern __shared__ char dync[];
    __nv_bfloat16* Wt = (__nv_bfloat16*)dync;        // [96 cols][WSTR]  (phase 1)
    __nv_bfloat16* Es = Wt + DD * WSTR;              // [128 rows][ESTRB] (phase 1)
    __nv_bfloat16* Ds = (__nv_bfloat16*)dync;        // [128][ESTRB] gathered Dh (phase 2)
    __shared__ float s_sum[DD], s_sq[DD], bsh[DD];
    __shared__ float s_esc[DD], s_esh[DD];
    __shared__ int s_src[128], s_dst[128];
    __shared__ float s_ef[128 * 4];
    __shared__ float s_wemb[4 * DD];
    __shared__ float s_bemb[DD];
    int t = threadIdx.x;
    int lane = t & 31, w = t >> 5;
    if (t < DD) {
        s_sum[t] = 0.f; s_sq[t] = 0.f; bsh[t] = b[t];
        if (apply)
            bn_scales(g_esum + (layer - 1) * DD, g_esq + (layer - 1) * DD,
                      eg, ebt, (double)EE, t, s_esc[t], s_esh[t]);
    }
    for (int i = t; i < DD * 12; i += 256) {
        int col = i / 12, kk = (i - (i / 12) * 12) * 8;
        *(uint4*)(Wt + col * WSTR + kk) = *(const uint4*)(Wtg + col * DD + kk);
    }
    int ebase = blockIdx.x * 128;   // EE % 128 == 0
    if (t < 128) { s_src[t] = g_srcp[ebase + t]; s_dst[t] = g_dstp[ebase + t]; }
    if (embed) {
        for (int i = t; i < 4 * DD; i += 256) s_wemb[i] = Wemb[i];
        if (t < DD) s_bemb[t] = bemb[t];
        if (t < 128) {
            int ei = g_eid[ebase + t];
            *(float4*)(s_ef + t * 4) = *(const float4*)(efeat + (size_t)ei * 4);
        }
    }
    __syncthreads();
    if (embed) {
        for (int i = t; i < 128 * 12; i += 256) {
            int r = i / 12, c8 = (i - (i / 12) * 12) * 8;
            size_t idx = (size_t)(ebase + r) * DD + c8;
            float4 f = *(const float4*)(s_ef + r * 4);
            float v[8];
#pragma unroll
            for (int j = 0; j < 8; j++) {
                int c = c8 + j;
                v[j] = s_bemb[c] + f.x * s_wemb[c] + f.y * s_wemb[DD + c]
                     + f.z * s_wemb[2 * DD + c] + f.w * s_wemb[3 * DD + c];
            }
            uint4 packed = f_to_bf8(v);
            *(uint4*)(g_e + idx) = packed;
            *(uint4*)(Es + r * ESTRB + c8) = packed;
        }
    } else {
        for (int i = t; i < 128 * 12; i += 256) {
            int r = i / 12, c8 = (i - (i / 12) * 12) * 8;
            size_t idx = (size_t)(ebase + r) * DD + c8;
            uint4 ue = *(const uint4*)(g_e + idx);
            if (apply) {
                float v[8], en[8];
                bf8_to_f(ue, v);
                uint4 un = *(const uint4*)(g_enew + idx);
                bf8_to_f(un, en);
#pragma unroll
                for (int j = 0; j < 8; j++)
                    v[j] += fmaxf(s_esc[c8 + j] * en[j] + s_esh[c8 + j], 0.f);
                uint4 packed = f_to_bf8(v);
                if (write_e) *(uint4*)(g_e + idx) = packed;
                *(uint4*)(Es + r * ESTRB + c8) = packed;
            } else {
                *(uint4*)(Es + r * ESTRB + c8) = ue;
            }
        }
    }
    __syncthreads();

    int mg = w >> 1, ng = w & 1;
    int m0 = mg * 32, n0 = ng * 48;
    int g = lane >> 2, c4 = lane & 3;
    float acc[2][6][4];
#pragma unroll
    for (int i = 0; i < 2; i++)
#pragma unroll
        for (int j = 0; j < 6; j++)
#pragma unroll
            for (int q = 0; q < 4; q++) acc[i][j][q] = 0.f;

#pragma unroll
    for (int k0 = 0; k0 < DD; k0 += 16) {
        unsigned a[2][4];
#pragma unroll
        for (int i = 0; i < 2; i++) {
            int rr = (m0 + i * 16 + g) * ESTRB;
            a[i][0] = *(const unsigned*)(Es + rr + k0 + 2 * c4);
            a[i][1] = *(const unsigned*)(Es + rr + 8 * ESTRB + k0 + 2 * c4);
            a[i][2] = *(const unsigned*)(Es + rr + k0 + 8 + 2 * c4);
            a[i][3] = *(const unsigned*)(Es + rr + 8 * ESTRB + k0 + 8 + 2 * c4);
        }
#pragma unroll
        for (int j = 0; j < 6; j++) {
            int col = n0 + 8 * j + g;
            unsigned b0 = *(const unsigned*)(Wt + col * WSTR + k0 + 2 * c4);
            unsigned b1 = *(const unsigned*)(Wt + col * WSTR + k0 + 8 + 2 * c4);
            MMA_BF16(acc[0][j], a[0], b0, b1);
            MMA_BF16(acc[1][j], a[1], b0, b1);
        }
    }
    __syncthreads();   // Wt/Es dead; recycle smem for Dh rows

    for (int i = t; i < 128 * 12; i += 256) {
        int r = i / 12, c8 = (i - (i / 12) * 12) * 8;
        *(uint4*)(Ds + r * ESTRB + c8) =
            *(const uint4*)(g_D + (size_t)s_src[r] * DD + c8);
    }
    __syncthreads();

    float cs[6][2], cq[6][2];
#pragma unroll
    for (int j = 0; j < 6; j++) { cs[j][0] = cs[j][1] = 0.f; cq[j][0] = cq[j][1] = 0.f; }
#pragma unroll
    for (int i = 0; i < 2; i++) {
#pragma unroll
        for (int half = 0; half < 2; half++) {
            int rl = m0 + i * 16 + half * 8 + g;
            size_t db = (size_t)s_dst[rl] * DD;
            size_t ob = (size_t)(ebase + rl) * DD;
#pragma unroll
            for (int j = 0; j < 6; j++) {
                int col = n0 + 8 * j + 2 * c4;
                float2 dh = __bfloat1622float2(*(const __nv_bfloat162*)(Ds + rl * ESTRB + col));
                float2 eh = __bfloat1622float2(*(const __nv_bfloat162*)(g_E + db + col));
                float v0 = acc[i][j][half * 2 + 0] + bsh[col]     + dh.x + eh.x;
                float v1 = acc[i][j][half * 2 + 1] + bsh[col + 1] + dh.y + eh.y;
                *(__nv_bfloat162*)(g_enew + ob + col) =
                    __float22bfloat162_rn(make_float2(v0, v1));
                cs[j][0] += v0; cs[j][1] += v1;
                cq[j][0] += v0 * v0; cq[j][1] += v1 * v1;
            }
        }
    }
    if (do_stats) {
#pragma unroll
        for (int off = 16; off >= 4; off >>= 1) {
#pragma unroll
            for (int j = 0; j < 6; j++) {
#pragma unroll
                for (int p = 0; p < 2; p++) {
                    cs[j][p] += __shfl_down_sync(0xffffffffu, cs[j][p], off);
                    cq[j][p] += __shfl_down_sync(0xffffffffu, cq[j][p], off);
                }
            }
        }
        if (lane < 4) {
#pragma unroll
            for (int j = 0; j < 6; j++) {
#pragma unroll
                for (int p = 0; p < 2; p++) {
                    int col = n0 + 8 * j + 2 * lane + p;
                    atomicAdd(&s_sum[col], cs[j][p]);
                    atomicAdd(&s_sq[col], cq[j][p]);
                }
            }
        }
        __syncthreads();
        if (t < DD) {
            atomicAdd(&g_esum[layer * DD + t], (double)s_sum[t]);
            atomicAdd(&g_esq[layer * DD + t], (double)s_sq[t]);
        }
    }
}

// ------------------------- aggregation (CSR, unroll x2) -----------------------
__global__ __launch_bounds__(256) void k_agg(int layer) {
    __shared__ float ssum[DD], ssq[DD];
    int t = threadIdx.x;
    if (t < DD) { ssum[t] = 0.f; ssq[t] = 0.f; }
    __syncthreads();
    int w = t >> 5, ln = t & 31;
    int v = blockIdx.x * 8 + w;
    float n0 = 0, n1 = 0, n2 = 0, d0 = 0, d1 = 0, d2 = 0;
    int p0 = g_ptr[v], p1 = g_ptr[v + 1];
    int p = p0;
    for (; p + 1 < p1; p += 2) {
        int sa = g_srcp[p], sb_ = g_srcp[p + 1];
        size_t ea = (size_t)p * DD, eb = (size_t)(p + 1) * DD;
        size_t sba = (size_t)sa * DD, sbb = (size_t)sb_ * DD;
        float xa0 = __bfloat162float(g_enew[ea + ln]);
        float xa1 = __bfloat162float(g_enew[ea + ln + 32]);
        float xa2 = __bfloat162float(g_enew[ea + ln + 64]);
        float xb0 = __bfloat162float(g_enew[eb + ln]);
        float xb1 = __bfloat162float(g_enew[eb + ln + 32]);
        float xb2 = __bfloat162float(g_enew[eb + ln + 64]);
        float ba0 = __bfloat162float(g_B[sba + ln]);
        float ba1 = __bfloat162float(g_B[sba + ln + 32]);
        float ba2 = __bfloat162float(g_B[sba + ln + 64]);
        float bb0 = __bfloat162float(g_B[sbb + ln]);
        float bb1 = __bfloat162float(g_B[sbb + ln + 32]);
        float bb2 = __bfloat162float(g_B[sbb + ln + 64]);
        float sa0 = __fdividef(1.f, 1.f + __expf(-xa0));
        float sa1 = __fdividef(1.f, 1.f + __expf(-xa1));
        float sa2 = __fdividef(1.f, 1.f + __expf(-xa2));
        float sb0 = __fdividef(1.f, 1.f + __expf(-xb0));
        float sb1 = __fdividef(1.f, 1.f + __expf(-xb1));
        float sb2 = __fdividef(1.f, 1.f + __expf(-xb2));
        n0 += sa0 * ba0; n0 += sb0 * bb0;
        n1 += sa1 * ba1; n1 += sb1 * bb1;
        n2 += sa2 * ba2; n2 += sb2 * bb2;
        d0 += sa0; d0 += sb0;
        d1 += sa1; d1 += sb1;
        d2 += sa2; d2 += sb2;
    }
    if (p < p1) {
        int s = g_srcp[p];
        size_t eb = (size_t)p * DD;
        size_t sb = (size_t)s * DD;
        float x0 = __bfloat162float(g_enew[eb + ln]);
        float x1 = __bfloat162float(g_enew[eb + ln + 32]);
        float x2 = __bfloat162float(g_enew[eb + ln + 64]);
        float s0 = __fdividef(1.f, 1.f + __expf(-x0));
        float s1 = __fdividef(1.f, 1.f + __expf(-x1));
        float s2 = __fdividef(1.f, 1.f + __expf(-x2));
        n0 += s0 * __bfloat162float(g_B[sb + ln]);
        n1 += s1 * __bfloat162float(g_B[sb + ln + 32]);
        n2 += s2 * __bfloat162float(g_B[sb + ln + 64]);
        d0 += s0; d1 += s1; d2 += s2;
    }
    size_t vb = (size_t)v * DD;
    float h0 = g_A[vb + ln]      + __fdividef(n0, d0 + 1e-6f);
    float h1 = g_A[vb + ln + 32] + __fdividef(n1, d1 + 1e-6f);
    float h2 = g_A[vb + ln + 64] + __fdividef(n2, d2 + 1e-6f);
    g_hnew[vb + ln] = h0; g_hnew[vb + ln + 32] = h1; g_hnew[vb + ln + 64] = h2;
    atomicAdd(&ssum[ln], h0);      atomicAdd(&ssum[ln + 32], h1); atomicAdd(&ssum[ln + 64], h2);
    atomicAdd(&ssq[ln], h0 * h0);  atomicAdd(&ssq[ln + 32], h1 * h1); atomicAdd(&ssq[ln + 64], h2 * h2);
    __syncthreads();
    if (t < DD) {
        atomicAdd(&g_hsum[layer * DD + t], (double)ssum[t]);
        atomicAdd(&g_hsq[layer * DD + t], (double)ssq[t]);
    }
}

// ------------------------- head -----------------------------------------------
__global__ __launch_bounds__(256) void k_head(const float* __restrict__ W1,
                                              const float* __restrict__ b1,
                                              const float* __restrict__ W2,
                                              const float* __restrict__ b2,
                                              const float* __restrict__ maxa,
                                              const float* __restrict__ hg,
                                              const float* __restrict__ hbt,
                                              float* __restrict__ out) {
    extern __shared__ float dyn[];
    float* W1s = dyn;
    float* Hs  = W1s + DD * HIDN;
    float* His = Hs + 32 * DD;
    float* W2s = His + 32 * 132;
    __shared__ float hsc[DD], hsh[DD];
    int t = threadIdx.x;
    if (t < DD)
        bn_scales(g_hsum + 3 * DD, g_hsq + 3 * DD, hg, hbt, (double)NN, t, hsc[t], hsh[t]);
    for (int i = t; i < DD * HIDN; i += 256) W1s[i] = W1[i];
    for (int i = t; i < HIDN * OUTN; i += 256) W2s[i] = W2[i];
    __syncthreads();
    int row0 = blockIdx.x * 32;
    for (int i = t; i < 32 * 24; i += 256) {
        int r = i / 24, c4 = (i - (i / 24) * 24) * 4;
        int gr = row0 + r;
        float4 v = make_float4(0.f, 0.f, 0.f, 0.f);
        if (gr < NN) {
            size_t idx = (size_t)gr * DD + c4;
            v = *(const float4*)(g_h + idx);
            float4 en = *(const float4*)(g_hnew + idx);
            v.x += fmaxf(hsc[c4 + 0] * en.x + hsh[c4 + 0], 0.f);
            v.y += fmaxf(hsc[c4 + 1] * en.y + hsh[c4 + 1], 0.f);
            v.z += fmaxf(hsc[c4 + 2] * en.z + hsh[c4 + 2], 0.f);
            v.w += fmaxf(hsc[c4 + 3] * en.w + hsh[c4 + 3], 0.f);
        }
        *(float4*)(Hs + r * DD + c4) = v;
    }
    __syncthreads();
    {
        int ng = t >> 5, hgr = t & 31;
        int r0 = ng * 4, c0 = hgr * 4;
        ull acc[4][2];
        float4 bv = *(const float4*)(b1 + c0);
        ull b01 = pk2(bv.x, bv.y), b23 = pk2(bv.z, bv.w);
#pragma unroll
        for (int r = 0; r < 4; r++) { acc[r][0] = b01; acc[r][1] = b23; }
#pragma unroll 4
        for (int k = 0; k < DD; k++) {
            ulonglong2 wv = *(const ulonglong2*)(W1s + k * HIDN + c0);
#pragma unroll
            for (int r = 0; r < 4; r++) {
                float x = Hs[(r0 + r) * DD + k];
                ull xx = pk2(x, x);
                acc[r][0] = fma2(xx, wv.x, acc[r][0]);
                acc[r][1] = fma2(xx, wv.y, acc[r][1]);
            }
        }
#pragma unroll
        for (int r = 0; r < 4; r++) {
            float2 a = upk(acc[r][0]), q = upk(acc[r][1]);
            His[(r0 + r) * 132 + c0 + 0] = fmaxf(a.x, 0.f);
            His[(r0 + r) * 132 + c0 + 1] = fmaxf(a.y, 0.f);
            His[(r0 + r) * 132 + c0 + 2] = fmaxf(q.x, 0.f);
            His[(r0 + r) * 132 + c0 + 3] = fmaxf(q.y, 0.f);
        }
    }
    __syncthreads();
    {
        int node = t >> 3, oc = t & 7;
        int gn = row0 + node;
        if (gn < NN) {
            float acc = b2[oc];
#pragma unroll 8
            for (int k = 0; k < HIDN; k++) acc += His[node * 132 + k] * W2s[k * OUTN + oc];
            out[(size_t)gn * OUTN + oc] = maxa[gn] * tanhf(acc);
        }
    }
}

// ------------------------- launch ---------------------------------------------
extern "C" void kernel_launch(void* const* d_in, const int* in_sizes, int n_in,
                              void* d_out, int out_size) {
    const float* h1      = (const float*)d_in[0];
    const float* h2      = (const float*)d_in[1];
    const float* z       = (const float*)d_in[2];
    const float* efeat   = (const float*)d_in[3];
    const float* maxa    = (const float*)d_in[4];
    const float* Wh_emb  = (const float*)d_in[5];
    const float* bh_emb  = (const float*)d_in[6];
    const float* We_emb  = (const float*)d_in[7];
    const float* be_emb  = (const float*)d_in[8];
    const float* WA      = (const float*)d_in[9];
    const float* bA      = (const float*)d_in[10];
    const float* WB      = (const float*)d_in[11];
    const float* bB      = (const float*)d_in[12];
    const float* WC      = (const float*)d_in[13];
    const float* bC      = (const float*)d_in[14];
    const float* WD      = (const float*)d_in[15];
    const float* bD      = (const float*)d_in[16];
    const float* WE      = (const float*)d_in[17];
    const float* bE      = (const float*)d_in[18];
    const float* bn_h_g  = (const float*)d_in[19];
    const float* bn_h_b  = (const float*)d_in[20];
    const float* bn_e_g  = (const float*)d_in[21];
    const float* bn_e_b  = (const float*)d_in[22];
    const float* W1      = (const float*)d_in[23];
    const float* b1      = (const float*)d_in[24];
    const float* W2      = (const float*)d_in[25];
    const float* b2      = (const float*)d_in[26];
    const int*   src     = (const int*)d_in[27];
    const int*   dst     = (const int*)d_in[28];
    float* out = (float*)d_out;

    static cudaStream_t s1 = nullptr;
    static cudaEvent_t ev0, evCSR, evDE[4], evAB[4];
    if (!s1) {
        cudaStreamCreateWithFlags(&s1, cudaStreamNonBlocking);
        cudaEventCreateWithFlags(&ev0, cudaEventDisableTiming);
        cudaEventCreateWithFlags(&evCSR, cudaEventDisableTiming);
        for (int i = 0; i < 4; i++) {
            cudaEventCreateWithFlags(&evDE[i], cudaEventDisableTiming);
            cudaEventCreateWithFlags(&evAB[i], cudaEventDisableTiming);
        }
    }

    float *WDE_base, *WAB_base;
    __nv_bfloat16* WtC_base;
    cudaGetSymbolAddress((void**)&WDE_base, g_WDE);
    cudaGetSymbolAddress((void**)&WAB_base, g_WAB);
    cudaGetSymbolAddress((void**)&WtC_base, g_WtC);

    cudaFuncSetAttribute(k_mat2, cudaFuncAttributeMaxDynamicSharedMemorySize, 110 * 1024);
    cudaFuncSetAttribute(k_edge, cudaFuncAttributeMaxDynamicSharedMemorySize, 64 * 1024);
    cudaFuncSetAttribute(k_head, cudaFuncAttributeMaxDynamicSharedMemorySize, 96 * 1024);

    const int smem_mat2 = (DD * WS2 + 64 * XSTR + 192) * 4;                     // 105216
    const int smem_edge = (DD * WSTR + 128 * ESTRB) * 2;                        // 46592
    const int smem_head = (DD * HIDN + 32 * DD + 32 * 132 + HIDN * OUTN) * 4;   // 82432

    k_zero<<<(NN + 255) / 256, 256>>>();
    cudaEventRecord(ev0, 0);
    cudaStreamWaitEvent(s1, ev0, 0);
    k_count<<<EE / 256, 256, 0, s1>>>(dst);
    k_scan1<<<NBS, 256, 0, s1>>>();
    k_scan2<<<1, 256, 0, s1>>>();
    k_scan3<<<NBS, 256, 0, s1>>>();
    k_fill<<<EE / 256, 256, 0, s1>>>(dst);
    k_sortperm<<<(NN + 127) / 128, 128, 0, s1>>>(src, dst);
    cudaEventRecord(evCSR, s1);

    const int prep_blks = EMB_BLKS + (184320 + 255) / 256;
    k_prep<<<prep_blks, 256>>>(h1, h2, z, Wh_emb, bh_emb, WA, WB, WC, WD, WE);

    const int ablk = (NN + 63) / 64;   // 782
    const int eblk = EE / 128;         // 6250

    for (int l = 0; l < 4; l++) {
        int lp = (l > 0) ? l - 1 : 0;
        k_mat2<<<ablk, 256, smem_mat2>>>(WDE_base + l * DD * 192,
                                         bD + l * DD, bE + l * DD,
                                         bn_h_g + lp * DD, bn_h_b + lp * DD,
                                         l, l >= 1 ? 1 : 0, 0);
        cudaEventRecord(evDE[l], 0);
        cudaStreamWaitEvent(s1, evDE[l], 0);
        k_mat2<<<ablk, 256, smem_mat2, s1>>>(WAB_base + l * DD * 192,
                                             bA + l * DD, bB + l * DD,
                                             bn_h_g, bn_h_b, l, 0, 1);
        cudaEventRecord(evAB[l], s1);

        if (l == 0) cudaStreamWaitEvent(0, evCSR, 0);
        int embed = (l == 0) ? 1 : 0;
        int apply = (l >= 1) ? 1 : 0;
        int write_e = (l >= 1 && l < 3) ? 1 : 0;
        int do_stats = (l < 3) ? 1 : 0;
        k_edge<<<eblk, 256, smem_edge>>>(WtC_base + l * DD * DD, bC + l * DD,
                                         efeat, We_emb, be_emb,
                                         bn_e_g + lp * DD, bn_e_b + lp * DD,
                                         l, embed, apply, write_e, do_stats);

        cudaStreamWaitEvent(0, evAB[l], 0);
        k_agg<<<NN / 8, 256>>>(l);
    }

    k_head<<<(NN + 31) / 32, 256, smem_head>>>(W1, b1, W2, b2, maxa,
                                               bn_h_g + 3 * DD, bn_h_b + 3 * DD, out);
}

// round 16
// speedup vs baseline: 1.1890x; 1.0007x over previous
#include <cuda_runtime.h>
#include <cuda_bf16.h>
#include <math.h>

#define NN 50000
#define EE 800000
#define DD 96
#define HIDN 128
#define OUTN 8
#define NBS 196    // scan blocks = ceil(NN/256)
#define WSTR 104   // bf16 smem stride (elements) for W^T  — conflict-free (edge)
#define ESTRB 104  // bf16 smem stride (elements) for E tile (edge)
#define XSTR 108   // f32/tf32 smem stride for X tile (mat kernels)
#define WS2 200    // f32/tf32 smem stride for 2-matrix concat W (mat kernels)
#define EMB_BLKS 18750  // (NN*DD+255)/256

typedef unsigned long long ull;

// ------------------------- device scratch (no allocs allowed) ----------------
__device__ float g_h[(size_t)NN * DD];
__device__ float g_hnew[(size_t)NN * DD];
__device__ float g_A[(size_t)NN * DD];             // f32 (residual-critical)
__device__ __nv_bfloat16 g_B[(size_t)NN * DD];     // gathered tables in bf16
__device__ __nv_bfloat16 g_D[(size_t)NN * DD];
__device__ __nv_bfloat16 g_E[(size_t)NN * DD];
__device__ __nv_bfloat16 g_e[(size_t)EE * DD];     // permuted (CSR dst order)
__device__ __nv_bfloat16 g_enew[(size_t)EE * DD];  // permuted
__device__ __nv_bfloat16 g_WtC[4 * DD * DD];       // pre-transposed bf16 WC per layer
__device__ float g_WDE[4 * DD * 192];              // tf32-prerounded [WD|WE] per layer
__device__ float g_WAB[4 * DD * 192];              // tf32-prerounded [WA|WB] per layer
__device__ int   g_cnt[NN];
__device__ int   g_ptr[NN + 1];
__device__ int   g_woff[NN];
__device__ int   g_eid[EE];
__device__ int   g_srcp[EE];
__device__ int   g_dstp[EE];
__device__ int   g_bsum[256];
__device__ int   g_boff[256];
// layer-indexed stats (no reset races)
__device__ double g_esum[4 * DD], g_esq[4 * DD], g_hsum[4 * DD], g_hsq[4 * DD];

// ------------------------- helpers -------------------------------------------
__device__ __forceinline__ ull pk2(float lo, float hi) {
    ull r; asm("mov.b64 %0,{%1,%2};" : "=l"(r) : "f"(lo), "f"(hi)); return r;
}
__device__ __forceinline__ ull fma2(ull a, ull b, ull c) {
    ull d; asm("fma.rn.f32x2 %0,%1,%2,%3;" : "=l"(d) : "l"(a), "l"(b), "l"(c)); return d;
}
__device__ __forceinline__ float2 upk(ull v) {
    float2 f; asm("mov.b64 {%0,%1},%2;" : "=f"(f.x), "=f"(f.y) : "l"(v)); return f;
}
__device__ __forceinline__ float tf32r(float x) {
    unsigned u; asm("cvt.rna.tf32.f32 %0,%1;" : "=r"(u) : "f"(x));
    return __uint_as_float(u);
}
#define MMA_TF32(d, a, b0_, b1_) \
    asm volatile("mma.sync.aligned.m16n8k8.row.col.f32.tf32.tf32.f32 " \
        "{%0,%1,%2,%3},{%4,%5,%6,%7},{%8,%9},{%0,%1,%2,%3};" \
        : "+f"(d[0]), "+f"(d[1]), "+f"(d[2]), "+f"(d[3]) \
        : "r"(a[0]), "r"(a[1]), "r"(a[2]), "r"(a[3]), "r"(b0_), "r"(b1_))
#define MMA_BF16(d, a, b0_, b1_) \
    asm volatile("mma.sync.aligned.m16n8k16.row.col.f32.bf16.bf16.f32 " \
        "{%0,%1,%2,%3},{%4,%5,%6,%7},{%8,%9},{%0,%1,%2,%3};" \
        : "+f"(d[0]), "+f"(d[1]), "+f"(d[2]), "+f"(d[3]) \
        : "r"(a[0]), "r"(a[1]), "r"(a[2]), "r"(a[3]), "r"(b0_), "r"(b1_))

__device__ __forceinline__ void bf8_to_f(const uint4& u, float* f) {
    const __nv_bfloat162* p = (const __nv_bfloat162*)&u;
#pragma unroll
    for (int j = 0; j < 4; j++) {
        float2 t = __bfloat1622float2(p[j]);
        f[2 * j] = t.x; f[2 * j + 1] = t.y;
    }
}
__device__ __forceinline__ uint4 f_to_bf8(const float* f) {
    uint4 u;
    __nv_bfloat162* p = (__nv_bfloat162*)&u;
#pragma unroll
    for (int j = 0; j < 4; j++)
        p[j] = __float22bfloat162_rn(make_float2(f[2 * j], f[2 * j + 1]));
    return u;
}
__device__ __forceinline__ void bn_scales(const double* sum, const double* sq,
                                          const float* gamma, const float* beta,
                                          double count, int c, float& sc, float& sh) {
    double s = sum[c], q = sq[c];
    double m = s / count;
    double var = q / count - m * m;
    sc = gamma[c] * rsqrtf((float)var + 1e-5f);
    sh = beta[c] - (float)m * sc;
}

// ------------------------- setup ----------------------------------------------
__global__ void k_zero() {
    int i = blockIdx.x * blockDim.x + threadIdx.x;
    if (i < NN) g_cnt[i] = 0;
    if (i < 4 * DD) { g_esum[i] = 0.0; g_esq[i] = 0.0; g_hsum[i] = 0.0; g_hsq[i] = 0.0; }
}

__global__ void k_prep(const float* __restrict__ h1, const float* __restrict__ h2,
                       const float* __restrict__ z,
                       const float* __restrict__ Wh, const float* __restrict__ bh,
                       const float* __restrict__ WA, const float* __restrict__ WB,
                       const float* __restrict__ WC, const float* __restrict__ WD,
                       const float* __restrict__ WE) {
    int t = threadIdx.x;
    if (blockIdx.x < EMB_BLKS) {
        __shared__ float Ws[26 * DD];
        for (int i = t; i < 26 * DD; i += 256) Ws[i] = Wh[i];
        __syncthreads();
        int idx = blockIdx.x * 256 + t;
        if (idx >= NN * DD) return;
        int r = idx / DD, c = idx - (idx / DD) * DD;
        float acc = bh[c];
#pragma unroll
        for (int k = 0; k < 6; k++)  acc += h1[r * 6 + k]  * Ws[k * DD + c];
#pragma unroll
        for (int k = 0; k < 4; k++)  acc += h2[r * 4 + k]  * Ws[(6 + k) * DD + c];
#pragma unroll
        for (int k = 0; k < 16; k++) acc += z[r * 16 + k]  * Ws[(10 + k) * DD + c];
        g_h[idx] = acc;
        return;
    }
    int j = (blockIdx.x - EMB_BLKS) * 256 + t;
    if (j < 73728) {
        int l = j / 18432, r = j - l * 18432;
        int k = r / 192, c = r - k * 192;
        int m = c / DD, cc = c - m * DD;
        const float* src = m ? WE : WD;
        g_WDE[j] = tf32r(src[(size_t)l * DD * DD + k * DD + cc]);
    } else if (j < 147456) {
        int i = j - 73728;
        int l = i / 18432, r = i - l * 18432;
        int k = r / 192, c = r - k * 192;
        int m = c / DD, cc = c - m * DD;
        const float* src = m ? WB : WA;
        g_WAB[i] = tf32r(src[(size_t)l * DD * DD + k * DD + cc]);
    } else if (j < 184320) {
        int i = j - 147456;
        int l = i / 9216, r = i - l * 9216;
        int k = r / DD, n = r - k * DD;
        g_WtC[l * DD * DD + n * DD + k] = __float2bfloat16(WC[(size_t)l * DD * DD + k * DD + n]);
    }
}

// ------------------------- CSR build ------------------------------------------
__global__ void k_count(const int* __restrict__ dst) {
    int i = blockIdx.x * blockDim.x + threadIdx.x;
    if (i < EE) atomicAdd(&g_cnt[dst[i]], 1);
}

__global__ void k_scan1() {
    __shared__ int sh[256];
    int t = threadIdx.x, b = blockIdx.x;
    int j = b * 256 + t;
    int v = (j < NN) ? g_cnt[j] : 0;
    sh[t] = v; __syncthreads();
    for (int off = 1; off < 256; off <<= 1) {
        int u = (t >= off) ? sh[t - off] : 0;
        __syncthreads();
        sh[t] += u;
        __syncthreads();
    }
    if (j < NN) g_ptr[j] = sh[t] - v;
    if (t == 255) g_bsum[b] = sh[t];
}

__global__ void k_scan2() {
    __shared__ int sh[256];
    int t = threadIdx.x;
    int v = (t < NBS) ? g_bsum[t] : 0;
    sh[t] = v; __syncthreads();
    for (int off = 1; off < 256; off <<= 1) {
        int u = (t >= off) ? sh[t - off] : 0;
        __syncthreads();
        sh[t] += u;
        __syncthreads();
    }
    g_boff[t] = sh[t] - v;
}

__global__ void k_scan3() {
    int j = blockIdx.x * blockDim.x + threadIdx.x;
    if (j < NN) {
        int p = g_ptr[j] + g_boff[j >> 8];
        g_ptr[j] = p; g_woff[j] = p;
    }
    if (j == 0) g_ptr[NN] = EE;
}

__global__ void k_fill(const int* __restrict__ dst) {
    int i = blockIdx.x * blockDim.x + threadIdx.x;
    if (i < EE) {
        int pos = atomicAdd(&g_woff[dst[i]], 1);
        g_eid[pos] = i;
    }
}

__global__ void k_sortperm(const int* __restrict__ src, const int* __restrict__ dst) {
    int v = blockIdx.x * blockDim.x + threadIdx.x;
    if (v >= NN) return;
    int lo = g_ptr[v], hi = g_ptr[v + 1];
    for (int i = lo + 1; i < hi; i++) {
        int key = g_eid[i]; int j = i - 1;
        while (j >= lo && g_eid[j] > key) { g_eid[j + 1] = g_eid[j]; j--; }
        g_eid[j + 1] = key;
    }
    for (int i = lo; i < hi; i++) {
        int ei = g_eid[i];
        g_srcp[i] = src[ei];
        g_dstp[i] = dst[ei];
    }
}

// ------------------------- node GEMM (tf32 MMA), 2-matrix variant -------------
__global__ __launch_bounds__(256) void k_mat2(const float* __restrict__ Wcat,
                                              const float* __restrict__ b0_,
                                              const float* __restrict__ b1_,
                                              const float* __restrict__ hg,
                                              const float* __restrict__ hbt,
                                              int layer, int apply, int isAB) {
    extern __shared__ float dyn[];
    float* Ws = dyn;
    float* Xs = dyn + DD * WS2;
    float* Bs = Xs + 64 * XSTR;
    __shared__ float shsc[DD], shsh[DD];
    int t = threadIdx.x;
    int lane = t & 31, w = t >> 5;
    if (apply && t < DD)
        bn_scales(g_hsum + (layer - 1) * DD, g_hsq + (layer - 1) * DD,
                  hg, hbt, (double)NN, t, shsc[t], shsh[t]);
    for (int i = t; i < DD * 48; i += 256) {
        int k = i / 48, c4 = (i - (i / 48) * 48) * 4;
        *(float4*)(Ws + k * WS2 + c4) = *(const float4*)(Wcat + k * 192 + c4);
    }
    for (int i = t; i < 192; i += 256) Bs[i] = (i < DD) ? b0_[i] : b1_[i - DD];
    __syncthreads();
    int row0 = blockIdx.x * 64;
    for (int i = t; i < 64 * 24; i += 256) {
        int r = i / 24, c4 = (i - (i / 24) * 24) * 4;
        int gr = row0 + r;
        float4 v = make_float4(0.f, 0.f, 0.f, 0.f);
        if (gr < NN) {
            size_t idx = (size_t)gr * DD + c4;
            v = *(const float4*)(g_h + idx);
            if (apply) {
                float4 en = *(const float4*)(g_hnew + idx);
                v.x += fmaxf(shsc[c4 + 0] * en.x + shsh[c4 + 0], 0.f);
                v.y += fmaxf(shsc[c4 + 1] * en.y + shsh[c4 + 1], 0.f);
                v.z += fmaxf(shsc[c4 + 2] * en.z + shsh[c4 + 2], 0.f);
                v.w += fmaxf(shsc[c4 + 3] * en.w + shsh[c4 + 3], 0.f);
                *(float4*)(g_h + idx) = v;
            }
        }
        v.x = tf32r(v.x); v.y = tf32r(v.y); v.z = tf32r(v.z); v.w = tf32r(v.w);
        *(float4*)(Xs + r * XSTR + c4) = v;
    }
    __syncthreads();

    int mg = w >> 2, ng = w & 3;
    int m0 = mg * 32, n0 = ng * 48;
    int g = lane >> 2, c4 = lane & 3;
    float acc[2][6][4];
#pragma unroll
    for (int i = 0; i < 2; i++)
#pragma unroll
        for (int j = 0; j < 6; j++)
#pragma unroll
            for (int q = 0; q < 4; q++) acc[i][j][q] = 0.f;

#pragma unroll
    for (int k0 = 0; k0 < DD; k0 += 8) {
        unsigned a[2][4];
#pragma unroll
        for (int i = 0; i < 2; i++) {
            int rr = (m0 + i * 16 + g) * XSTR;
            a[i][0] = __float_as_uint(Xs[rr + k0 + c4]);
            a[i][1] = __float_as_uint(Xs[rr + 8 * XSTR + k0 + c4]);
            a[i][2] = __float_as_uint(Xs[rr + k0 + 4 + c4]);
            a[i][3] = __float_as_uint(Xs[rr + 8 * XSTR + k0 + 4 + c4]);
        }
#pragma unroll
        for (int j = 0; j < 6; j++) {
            int col = n0 + 8 * j + g;
            unsigned b0 = __float_as_uint(Ws[(k0 + c4) * WS2 + col]);
            unsigned b1 = __float_as_uint(Ws[(k0 + 4 + c4) * WS2 + col]);
            MMA_TF32(acc[0][j], a[0], b0, b1);
            MMA_TF32(acc[1][j], a[1], b0, b1);
        }
    }

    int m = n0 / DD;
    int ncc = n0 - m * DD;
    __nv_bfloat16* outb = isAB ? g_B : (m == 0 ? g_D : g_E);
    int is_f32 = (isAB && m == 0);
#pragma unroll
    for (int i = 0; i < 2; i++) {
#pragma unroll
        for (int half = 0; half < 2; half++) {
            int rl = m0 + i * 16 + half * 8 + g;
            int gr = row0 + rl;
            if (gr < NN) {
#pragma unroll
                for (int j = 0; j < 6; j++) {
                    int col = n0 + 8 * j + 2 * c4;
                    int cc = ncc + 8 * j + 2 * c4;
                    float v0 = acc[i][j][half * 2 + 0] + Bs[col];
                    float v1 = acc[i][j][half * 2 + 1] + Bs[col + 1];
                    if (is_f32) {
                        *(float2*)(g_A + (size_t)gr * DD + cc) = make_float2(v0, v1);
                    } else {
                        *(__nv_bfloat162*)(outb + (size_t)gr * DD + cc) =
                            __float22bfloat162_rn(make_float2(v0, v1));
                    }
                }
            }
        }
    }
}

// ------------------------- edge kernel: 128 edges/block, bf16 MMA -------------
// (R13 winning shape: both Dh and Eh staged in recycled smem.)
__global__ __launch_bounds__(256) void k_edge(const __nv_bfloat16* __restrict__ Wtg,
                                              const float* __restrict__ b,
                                              const float* __restrict__ efeat,
                                              const float* __restrict__ Wemb,
                                              const float* __restrict__ bemb,
                                              const float* __restrict__ eg,
                                              const float* __restrict__ ebt,
                                              int layer, int embed, int apply,
                                              int write_e, int do_stats) {
    extern __shared__ char dync[];
    __nv_bfloat16* Wt = (__nv_bfloat16*)dync;        // [96 cols][WSTR]  (phase 1)
    __nv_bfloat16* Es = Wt + DD * WSTR;              // [128 rows][ESTRB] (phase 1)
    __nv_bfloat16* Ds  = (__nv_bfloat16*)dync;       // [128][ESTRB] gathered Dh (phase 2)
    __nv_bfloat16* Eh2 = Ds + 128 * ESTRB;           // [128][ESTRB] gathered Eh (phase 2)
    __shared__ float s_sum[DD], s_sq[DD], bsh[DD];
    __shared__ float s_esc[DD], s_esh[DD];
    __shared__ int s_src[128], s_dst[128];
    __shared__ float s_ef[128 * 4];
    __shared__ float s_wemb[4 * DD];
    __shared__ float s_bemb[DD];
    int t = threadIdx.x;
    int lane = t & 31, w = t >> 5;
    if (t < DD) {
        s_sum[t] = 0.f; s_sq[t] = 0.f; bsh[t] = b[t];
        if (apply)
            bn_scales(g_esum + (layer - 1) * DD, g_esq + (layer - 1) * DD,
                      eg, ebt, (double)EE, t, s_esc[t], s_esh[t]);
    }
    for (int i = t; i < DD * 12; i += 256) {
        int col = i / 12, kk = (i - (i / 12) * 12) * 8;
        *(uint4*)(Wt + col * WSTR + kk) = *(const uint4*)(Wtg + col * DD + kk);
    }
    int ebase = blockIdx.x * 128;   // EE % 128 == 0
    if (t < 128) { s_src[t] = g_srcp[ebase + t]; s_dst[t] = g_dstp[ebase + t]; }
    if (embed) {
        for (int i = t; i < 4 * DD; i += 256) s_wemb[i] = Wemb[i];
        if (t < DD) s_bemb[t] = bemb[t];
        if (t < 128) {
            int ei = g_eid[ebase + t];
            *(float4*)(s_ef + t * 4) = *(const float4*)(efeat + (size_t)ei * 4);
        }
    }
    __syncthreads();
    if (embed) {
        for (int i = t; i < 128 * 12; i += 256) {
            int r = i / 12, c8 = (i - (i / 12) * 12) * 8;
            size_t idx = (size_t)(ebase + r) * DD + c8;
            float4 f = *(const float4*)(s_ef + r * 4);
            float v[8];
#pragma unroll
            for (int j = 0; j < 8; j++) {
                int c = c8 + j;
                v[j] = s_bemb[c] + f.x * s_wemb[c] + f.y * s_wemb[DD + c]
                     + f.z * s_wemb[2 * DD + c] + f.w * s_wemb[3 * DD + c];
            }
            uint4 packed = f_to_bf8(v);
            *(uint4*)(g_e + idx) = packed;
            *(uint4*)(Es + r * ESTRB + c8) = packed;
        }
    } else {
        for (int i = t; i < 128 * 12; i += 256) {
            int r = i / 12, c8 = (i - (i / 12) * 12) * 8;
            size_t idx = (size_t)(ebase + r) * DD + c8;
            uint4 ue = *(const uint4*)(g_e + idx);
            if (apply) {
                float v[8], en[8];
                bf8_to_f(ue, v);
                uint4 un = *(const uint4*)(g_enew + idx);
                bf8_to_f(un, en);
#pragma unroll
                for (int j = 0; j < 8; j++)
                    v[j] += fmaxf(s_esc[c8 + j] * en[j] + s_esh[c8 + j], 0.f);
                uint4 packed = f_to_bf8(v);
                if (write_e) *(uint4*)(g_e + idx) = packed;
                *(uint4*)(Es + r * ESTRB + c8) = packed;
            } else {
                *(uint4*)(Es + r * ESTRB + c8) = ue;
            }
        }
    }
    __syncthreads();

    int mg = w >> 1, ng = w & 1;
    int m0 = mg * 32, n0 = ng * 48;
    int g = lane >> 2, c4 = lane & 3;
    float acc[2][6][4];
#pragma unroll
    for (int i = 0; i < 2; i++)
#pragma unroll
        for (int j = 0; j < 6; j++)
#pragma unroll
            for (int q = 0; q < 4; q++) acc[i][j][q] = 0.f;

#pragma unroll
    for (int k0 = 0; k0 < DD; k0 += 16) {
        unsigned a[2][4];
#pragma unroll
        for (int i = 0; i < 2; i++) {
            int rr = (m0 + i * 16 + g) * ESTRB;
            a[i][0] = *(const unsigned*)(Es + rr + k0 + 2 * c4);
            a[i][1] = *(const unsigned*)(Es + rr + 8 * ESTRB + k0 + 2 * c4);
            a[i][2] = *(const unsigned*)(Es + rr + k0 + 8 + 2 * c4);
            a[i][3] = *(const unsigned*)(Es + rr + 8 * ESTRB + k0 + 8 + 2 * c4);
        }
#pragma unroll
        for (int j = 0; j < 6; j++) {
            int col = n0 + 8 * j + g;
            unsigned b0 = *(const unsigned*)(Wt + col * WSTR + k0 + 2 * c4);
            unsigned b1 = *(const unsigned*)(Wt + col * WSTR + k0 + 8 + 2 * c4);
            MMA_BF16(acc[0][j], a[0], b0, b1);
            MMA_BF16(acc[1][j], a[1], b0, b1);
        }
    }
    __syncthreads();   // Wt/Es dead; recycle smem for gathered rows

    for (int i = t; i < 128 * 12; i += 256) {
        int r = i / 12, c8 = (i - (i / 12) * 12) * 8;
        uint4 dv = *(const uint4*)(g_D + (size_t)s_src[r] * DD + c8);
        uint4 ev = *(const uint4*)(g_E + (size_t)s_dst[r] * DD + c8);
        *(uint4*)(Ds  + r * ESTRB + c8) = dv;
        *(uint4*)(Eh2 + r * ESTRB + c8) = ev;
    }
    __syncthreads();

    float cs[6][2], cq[6][2];
#pragma unroll
    for (int j = 0; j < 6; j++) { cs[j][0] = cs[j][1] = 0.f; cq[j][0] = cq[j][1] = 0.f; }
#pragma unroll
    for (int i = 0; i < 2; i++) {
#pragma unroll
        for (int half = 0; half < 2; half++) {
            int rl = m0 + i * 16 + half * 8 + g;
            size_t ob = (size_t)(ebase + rl) * DD;
#pragma unroll
            for (int j = 0; j < 6; j++) {
                int col = n0 + 8 * j + 2 * c4;
                float2 dh = __bfloat1622float2(*(const __nv_bfloat162*)(Ds  + rl * ESTRB + col));
                float2 eh = __bfloat1622float2(*(const __nv_bfloat162*)(Eh2 + rl * ESTRB + col));
                float v0 = acc[i][j][half * 2 + 0] + bsh[col]     + dh.x + eh.x;
                float v1 = acc[i][j][half * 2 + 1] + bsh[col + 1] + dh.y + eh.y;
                *(__nv_bfloat162*)(g_enew + ob + col) =
                    __float22bfloat162_rn(make_float2(v0, v1));
                cs[j][0] += v0; cs[j][1] += v1;
                cq[j][0] += v0 * v0; cq[j][1] += v1 * v1;
            }
        }
    }
    if (do_stats) {
#pragma unroll
        for (int off = 16; off >= 4; off >>= 1) {
#pragma unroll
            for (int j = 0; j < 6; j++) {
#pragma unroll
                for (int p = 0; p < 2; p++) {
                    cs[j][p] += __shfl_down_sync(0xffffffffu, cs[j][p], off);
                    cq[j][p] += __shfl_down_sync(0xffffffffu, cq[j][p], off);
                }
            }
        }
        if (lane < 4) {
#pragma unroll
            for (int j = 0; j < 6; j++) {
#pragma unroll
                for (int p = 0; p < 2; p++) {
                    int col = n0 + 8 * j + 2 * lane + p;
                    atomicAdd(&s_sum[col], cs[j][p]);
                    atomicAdd(&s_sq[col], cq[j][p]);
                }
            }
        }
        __syncthreads();
        if (t < DD) {
            atomicAdd(&g_esum[layer * DD + t], (double)s_sum[t]);
            atomicAdd(&g_esq[layer * DD + t], (double)s_sq[t]);
        }
    }
}

// ------------------------- aggregation (CSR, unroll x4) -----------------------
__global__ __launch_bounds__(256) void k_agg(int layer) {
    __shared__ float ssum[DD], ssq[DD];
    int t = threadIdx.x;
    if (t < DD) { ssum[t] = 0.f; ssq[t] = 0.f; }
    __syncthreads();
    int w = t >> 5, ln = t & 31;
    int v = blockIdx.x * 8 + w;
    float n0 = 0, n1 = 0, n2 = 0, d0 = 0, d1 = 0, d2 = 0;
    int p0 = g_ptr[v], p1 = g_ptr[v + 1];
    int p = p0;
    for (; p + 3 < p1; p += 4) {
        float x[4][3], bb[4][3];
#pragma unroll
        for (int u = 0; u < 4; u++) {
            size_t eb = (size_t)(p + u) * DD;
            size_t sb = (size_t)g_srcp[p + u] * DD;
            x[u][0] = __bfloat162float(g_enew[eb + ln]);
            x[u][1] = __bfloat162float(g_enew[eb + ln + 32]);
            x[u][2] = __bfloat162float(g_enew[eb + ln + 64]);
            bb[u][0] = __bfloat162float(g_B[sb + ln]);
            bb[u][1] = __bfloat162float(g_B[sb + ln + 32]);
            bb[u][2] = __bfloat162float(g_B[sb + ln + 64]);
        }
#pragma unroll
        for (int u = 0; u < 4; u++) {
            float s0 = __fdividef(1.f, 1.f + __expf(-x[u][0]));
            float s1 = __fdividef(1.f, 1.f + __expf(-x[u][1]));
            float s2 = __fdividef(1.f, 1.f + __expf(-x[u][2]));
            n0 += s0 * bb[u][0]; n1 += s1 * bb[u][1]; n2 += s2 * bb[u][2];
            d0 += s0; d1 += s1; d2 += s2;
        }
    }
    for (; p < p1; p++) {
        int s = g_srcp[p];
        size_t eb = (size_t)p * DD;
        size_t sb = (size_t)s * DD;
        float x0 = __bfloat162float(g_enew[eb + ln]);
        float x1 = __bfloat162float(g_enew[eb + ln + 32]);
        float x2 = __bfloat162float(g_enew[eb + ln + 64]);
        float s0 = __fdividef(1.f, 1.f + __expf(-x0));
        float s1 = __fdividef(1.f, 1.f + __expf(-x1));
        float s2 = __fdividef(1.f, 1.f + __expf(-x2));
        n0 += s0 * __bfloat162float(g_B[sb + ln]);
        n1 += s1 * __bfloat162float(g_B[sb + ln + 32]);
        n2 += s2 * __bfloat162float(g_B[sb + ln + 64]);
        d0 += s0; d1 += s1; d2 += s2;
    }
    size_t vb = (size_t)v * DD;
    float h0 = g_A[vb + ln]      + __fdividef(n0, d0 + 1e-6f);
    float h1 = g_A[vb + ln + 32] + __fdividef(n1, d1 + 1e-6f);
    float h2 = g_A[vb + ln + 64] + __fdividef(n2, d2 + 1e-6f);
    g_hnew[vb + ln] = h0; g_hnew[vb + ln + 32] = h1; g_hnew[vb + ln + 64] = h2;
    atomicAdd(&ssum[ln], h0);      atomicAdd(&ssum[ln + 32], h1); atomicAdd(&ssum[ln + 64], h2);
    atomicAdd(&ssq[ln], h0 * h0);  atomicAdd(&ssq[ln + 32], h1 * h1); atomicAdd(&ssq[ln + 64], h2 * h2);
    __syncthreads();
    if (t < DD) {
        atomicAdd(&g_hsum[layer * DD + t], (double)ssum[t]);
        atomicAdd(&g_hsq[layer * DD + t], (double)ssq[t]);
    }
}

// ------------------------- head -----------------------------------------------
__global__ __launch_bounds__(256) void k_head(const float* __restrict__ W1,
                                              const float* __restrict__ b1,
                                              const float* __restrict__ W2,
                                              const float* __restrict__ b2,
                                              const float* __restrict__ maxa,
                                              const float* __restrict__ hg,
                                              const float* __restrict__ hbt,
                                              float* __restrict__ out) {
    extern __shared__ float dyn[];
    float* W1s = dyn;
    float* Hs  = W1s + DD * HIDN;
    float* His = Hs + 32 * DD;
    float* W2s = His + 32 * 132;
    __shared__ float hsc[DD], hsh[DD];
    int t = threadIdx.x;
    if (t < DD)
        bn_scales(g_hsum + 3 * DD, g_hsq + 3 * DD, hg, hbt, (double)NN, t, hsc[t], hsh[t]);
    for (int i = t; i < DD * HIDN; i += 256) W1s[i] = W1[i];
    for (int i = t; i < HIDN * OUTN; i += 256) W2s[i] = W2[i];
    __syncthreads();
    int row0 = blockIdx.x * 32;
    for (int i = t; i < 32 * 24; i += 256) {
        int r = i / 24, c4 = (i - (i / 24) * 24) * 4;
        int gr = row0 + r;
        float4 v = make_float4(0.f, 0.f, 0.f, 0.f);
        if (gr < NN) {
            size_t idx = (size_t)gr * DD + c4;
            v = *(const float4*)(g_h + idx);
            float4 en = *(const float4*)(g_hnew + idx);
            v.x += fmaxf(hsc[c4 + 0] * en.x + hsh[c4 + 0], 0.f);
            v.y += fmaxf(hsc[c4 + 1] * en.y + hsh[c4 + 1], 0.f);
            v.z += fmaxf(hsc[c4 + 2] * en.z + hsh[c4 + 2], 0.f);
            v.w += fmaxf(hsc[c4 + 3] * en.w + hsh[c4 + 3], 0.f);
        }
        *(float4*)(Hs + r * DD + c4) = v;
    }
    __syncthreads();
    {
        int ng = t >> 5, hgr = t & 31;
        int r0 = ng * 4, c0 = hgr * 4;
        ull acc[4][2];
        float4 bv = *(const float4*)(b1 + c0);
        ull b01 = pk2(bv.x, bv.y), b23 = pk2(bv.z, bv.w);
#pragma unroll
        for (int r = 0; r < 4; r++) { acc[r][0] = b01; acc[r][1] = b23; }
#pragma unroll 4
        for (int k = 0; k < DD; k++) {
            ulonglong2 wv = *(const ulonglong2*)(W1s + k * HIDN + c0);
#pragma unroll
            for (int r = 0; r < 4; r++) {
                float x = Hs[(r0 + r) * DD + k];
                ull xx = pk2(x, x);
                acc[r][0] = fma2(xx, wv.x, acc[r][0]);
                acc[r][1] = fma2(xx, wv.y, acc[r][1]);
            }
        }
#pragma unroll
        for (int r = 0; r < 4; r++) {
            float2 a = upk(acc[r][0]), q = upk(acc[r][1]);
            His[(r0 + r) * 132 + c0 + 0] = fmaxf(a.x, 0.f);
            His[(r0 + r) * 132 + c0 + 1] = fmaxf(a.y, 0.f);
            His[(r0 + r) * 132 + c0 + 2] = fmaxf(q.x, 0.f);
            His[(r0 + r) * 132 + c0 + 3] = fmaxf(q.y, 0.f);
        }
    }
    __syncthreads();
    {
        int node = t >> 3, oc = t & 7;
        int gn = row0 + node;
        if (gn < NN) {
            float acc = b2[oc];
#pragma unroll 8
            for (int k = 0; k < HIDN; k++) acc += His[node * 132 + k] * W2s[k * OUTN + oc];
            out[(size_t)gn * OUTN + oc] = maxa[gn] * tanhf(acc);
        }
    }
}

// ------------------------- launch ---------------------------------------------
extern "C" void kernel_launch(void* const* d_in, const int* in_sizes, int n_in,
                              void* d_out, int out_size) {
    const float* h1      = (const float*)d_in[0];
    const float* h2      = (const float*)d_in[1];
    const float* z       = (const float*)d_in[2];
    const float* efeat   = (const float*)d_in[3];
    const float* maxa    = (const float*)d_in[4];
    const float* Wh_emb  = (const float*)d_in[5];
    const float* bh_emb  = (const float*)d_in[6];
    const float* We_emb  = (const float*)d_in[7];
    const float* be_emb  = (const float*)d_in[8];
    const float* WA      = (const float*)d_in[9];
    const float* bA      = (const float*)d_in[10];
    const float* WB      = (const float*)d_in[11];
    const float* bB      = (const float*)d_in[12];
    const float* WC      = (const float*)d_in[13];
    const float* bC      = (const float*)d_in[14];
    const float* WD      = (const float*)d_in[15];
    const float* bD      = (const float*)d_in[16];
    const float* WE      = (const float*)d_in[17];
    const float* bE      = (const float*)d_in[18];
    const float* bn_h_g  = (const float*)d_in[19];
    const float* bn_h_b  = (const float*)d_in[20];
    const float* bn_e_g  = (const float*)d_in[21];
    const float* bn_e_b  = (const float*)d_in[22];
    const float* W1      = (const float*)d_in[23];
    const float* b1      = (const float*)d_in[24];
    const float* W2      = (const float*)d_in[25];
    const float* b2      = (const float*)d_in[26];
    const int*   src     = (const int*)d_in[27];
    const int*   dst     = (const int*)d_in[28];
    float* out = (float*)d_out;

    static cudaStream_t s1 = nullptr;
    static cudaEvent_t ev0, evCSR, evDE[4], evAB[4];
    if (!s1) {
        cudaStreamCreateWithFlags(&s1, cudaStreamNonBlocking);
        cudaEventCreateWithFlags(&ev0, cudaEventDisableTiming);
        cudaEventCreateWithFlags(&evCSR, cudaEventDisableTiming);
        for (int i = 0; i < 4; i++) {
            cudaEventCreateWithFlags(&evDE[i], cudaEventDisableTiming);
            cudaEventCreateWithFlags(&evAB[i], cudaEventDisableTiming);
        }
    }

    float *WDE_base, *WAB_base;
    __nv_bfloat16* WtC_base;
    cudaGetSymbolAddress((void**)&WDE_base, g_WDE);
    cudaGetSymbolAddress((void**)&WAB_base, g_WAB);
    cudaGetSymbolAddress((void**)&WtC_base, g_WtC);

    cudaFuncSetAttribute(k_mat2, cudaFuncAttributeMaxDynamicSharedMemorySize, 110 * 1024);
    cudaFuncSetAttribute(k_edge, cudaFuncAttributeMaxDynamicSharedMemorySize, 64 * 1024);
    cudaFuncSetAttribute(k_head, cudaFuncAttributeMaxDynamicSharedMemorySize, 96 * 1024);

    const int smem_mat2 = (DD * WS2 + 64 * XSTR + 192) * 4;                     // 105216
    int smem_edge = (DD * WSTR + 128 * ESTRB) * 2;                              // 46592 (phase 1)
    int smem_p2   = 2 * 128 * ESTRB * 2;                                        // 53248 (phase 2)
    if (smem_p2 > smem_edge) smem_edge = smem_p2;
    const int smem_head = (DD * HIDN + 32 * DD + 32 * 132 + HIDN * OUTN) * 4;   // 82432

    k_zero<<<(NN + 255) / 256, 256>>>();
    cudaEventRecord(ev0, 0);
    cudaStreamWaitEvent(s1, ev0, 0);
    k_count<<<EE / 256, 256, 0, s1>>>(dst);
    k_scan1<<<NBS, 256, 0, s1>>>();
    k_scan2<<<1, 256, 0, s1>>>();
    k_scan3<<<NBS, 256, 0, s1>>>();
    k_fill<<<EE / 256, 256, 0, s1>>>(dst);
    k_sortperm<<<(NN + 127) / 128, 128, 0, s1>>>(src, dst);
    cudaEventRecord(evCSR, s1);

    const int prep_blks = EMB_BLKS + (184320 + 255) / 256;
    k_prep<<<prep_blks, 256>>>(h1, h2, z, Wh_emb, bh_emb, WA, WB, WC, WD, WE);

    const int ablk = (NN + 63) / 64;   // 782
    const int eblk = EE / 128;         // 6250

    for (int l = 0; l < 4; l++) {
        int lp = (l > 0) ? l - 1 : 0;
        k_mat2<<<ablk, 256, smem_mat2>>>(WDE_base + l * DD * 192,
                                         bD + l * DD, bE + l * DD,
                                         bn_h_g + lp * DD, bn_h_b + lp * DD,
                                         l, l >= 1 ? 1 : 0, 0);
        cudaEventRecord(evDE[l], 0);
        cudaStreamWaitEvent(s1, evDE[l], 0);
        k_mat2<<<ablk, 256, smem_mat2, s1>>>(WAB_base + l * DD * 192,
                                             bA + l * DD, bB + l * DD,
                                             bn_h_g, bn_h_b, l, 0, 1);
        cudaEventRecord(evAB[l], s1);

        if (l == 0) cudaStreamWaitEvent(0, evCSR, 0);
        int embed = (l == 0) ? 1 : 0;
        int apply = (l >= 1) ? 1 : 0;
        int write_e = (l >= 1 && l < 3) ? 1 : 0;
        int do_stats = (l < 3) ? 1 : 0;
        k_edge<<<eblk, 256, smem_edge>>>(WtC_base + l * DD * DD, bC + l * DD,
                                         efeat, We_emb, be_emb,
                                         bn_e_g + lp * DD, bn_e_b + lp * DD,
                                         l, embed, apply, write_e, do_stats);

        cudaStreamWaitEvent(0, evAB[l], 0);
        k_agg<<<NN / 8, 256>>>(l);
    }

    k_head<<<(NN + 31) / 32, 256, smem_head>>>(W1, b1, W2, b2, maxa,
                                               bn_h_g + 3 * DD, bn_h_b + 3 * DD, out);
}